// round 4
// baseline (speedup 1.0000x reference)
#include <cuda_runtime.h>
#include <cstdint>

#define BB 4
#define NN 4096
#define NSAMP 1024
#define KNB 32
#define MTOT (BB*NSAMP*KNB)   // 131072 positions

// ---------------- scratch (device globals; no allocations allowed) ------------
__device__ float g_w21[256*6];
__device__ int   g_knn[BB*NSAMP*KNB];
__device__ float g_y1[(size_t)256*MTOT];   // conv1 output pre-BN   (134MB)
__device__ float g_xm[256*BB*NSAMP];       // max over k of BN2-ReLU
__device__ float g_h3[512*BB*NSAMP];       // w3a @ xm
__device__ float g_y3[(size_t)512*MTOT];   // conv3 output pre-BN   (268MB)
__device__ float g_y4[(size_t)256*MTOT];   // conv4 output pre-BN   (134MB)
__device__ float g_sum[512], g_sq[512];
__device__ float g_s2[256], g_t2[256];
__device__ float g_s3[512], g_t3[512];
__device__ float g_s4[256], g_t4[256];

// ---------------- helpers ----------------------------------------------------
__device__ __forceinline__ unsigned long long dup2(float a) {
    unsigned int u = __float_as_uint(a);
    return ((unsigned long long)u << 32) | (unsigned long long)u;
}
__device__ __forceinline__ unsigned int fmono(float f) {
    unsigned int u = __float_as_uint(f);
    return (u & 0x80000000u) ? ~u : (u | 0x80000000u);
}

// ---------------- w21 = w2 @ w1 (256x6), tiny --------------------------------
__global__ void k_w21(const float* __restrict__ w1, const float* __restrict__ w2) {
    int o = threadIdx.x;
    float acc[6] = {0.f,0.f,0.f,0.f,0.f,0.f};
    for (int c = 0; c < 256; ++c) {
        float w = w2[o*256 + c];
        #pragma unroll
        for (int i = 0; i < 6; ++i) acc[i] = fmaf(w, w1[c*6+i], acc[i]);
    }
    #pragma unroll
    for (int i = 0; i < 6; ++i) g_w21[o*6+i] = acc[i];
}

// ---------------- FPS: one block per batch, 1024 thr, 4 pts/thr --------------
__global__ void k_fps(const float* __restrict__ p, float* __restrict__ outC) {
    int b = blockIdx.x;
    const float* pb = p + b*NN*3;
    int t = threadIdx.x;
    float px[4], py[4], pz[4], dm[4];
    #pragma unroll
    for (int j = 0; j < 4; ++j) {
        int i = t + j*1024;
        px[j] = pb[i*3]; py[j] = pb[i*3+1]; pz[j] = pb[i*3+2];
        dm[j] = 1e10f;
    }
    __shared__ float s_c[3];
    __shared__ float s_v[32];
    __shared__ int   s_i[32];
    __shared__ int   s_far;
    int far = 0;
    int lane = t & 31, w = t >> 5;
    for (int it = 0; it < NSAMP; ++it) {
        if (t == 0) {
            float cx = pb[far*3], cy = pb[far*3+1], cz = pb[far*3+2];
            s_c[0] = cx; s_c[1] = cy; s_c[2] = cz;
            float* o = outC + (b*NSAMP + it)*3;
            o[0] = cx; o[1] = cy; o[2] = cz;
        }
        __syncthreads();
        float cx = s_c[0], cy = s_c[1], cz = s_c[2];
        float best = -1.0f; int bi = 0;
        #pragma unroll
        for (int j = 0; j < 4; ++j) {
            float dx = px[j]-cx, dy = py[j]-cy, dz = pz[j]-cz;
            float d  = fmaf(dz, dz, fmaf(dy, dy, dx*dx));
            float nd = fminf(dm[j], d);
            dm[j] = nd;
            if (nd > best) { best = nd; bi = t + j*1024; }
        }
        #pragma unroll
        for (int off = 16; off; off >>= 1) {
            float ov = __shfl_down_sync(0xffffffffu, best, off);
            int   oi = __shfl_down_sync(0xffffffffu, bi,   off);
            if (ov > best || (ov == best && oi < bi)) { best = ov; bi = oi; }
        }
        if (lane == 0) { s_v[w] = best; s_i[w] = bi; }
        __syncthreads();
        if (w == 0) {
            best = s_v[lane]; bi = s_i[lane];
            #pragma unroll
            for (int off = 16; off; off >>= 1) {
                float ov = __shfl_down_sync(0xffffffffu, best, off);
                int   oi = __shfl_down_sync(0xffffffffu, bi,   off);
                if (ov > best || (ov == best && oi < bi)) { best = ov; bi = oi; }
            }
            if (lane == 0) s_far = bi;
        }
        __syncthreads();
        far = s_far;
    }
}

// ---------------- KNN: one block (128 thr) per centroid ----------------------
__global__ void k_knn(const float* __restrict__ p, const float* __restrict__ cent) {
    int cid = blockIdx.x;                 // b*NSAMP + s
    int b = cid >> 10;
    const float* pb = p + b*NN*3;
    int t = threadIdx.x;                  // 128
    float cx = cent[cid*3], cy = cent[cid*3+1], cz = cent[cid*3+2];
    float cn = cx*cx + cy*cy + cz*cz;
    unsigned long long key[32];
    #pragma unroll
    for (int j = 0; j < 32; ++j) {
        int i = j*128 + t;
        float x = pb[i*3], y = pb[i*3+1], z = pb[i*3+2];
        float pn = x*x + y*y + z*z;
        float dot = fmaf(cx, x, fmaf(cy, y, cz*z));
        float d2  = fmaf(-2.0f, dot, cn + pn);
        key[j] = ((unsigned long long)fmono(d2) << 32) | (unsigned int)i;
    }
    __shared__ unsigned long long s_part[4];
    __shared__ unsigned long long s_prev;
    unsigned long long prev = 0ull;
    int w = t >> 5, lane = t & 31;
    for (int r = 0; r < KNB; ++r) {
        unsigned long long best = ~0ull;
        #pragma unroll
        for (int j = 0; j < 32; ++j) {
            unsigned long long k = key[j];
            if (k > prev && k < best) best = k;
        }
        #pragma unroll
        for (int off = 16; off; off >>= 1) {
            unsigned long long o = __shfl_down_sync(0xffffffffu, best, off);
            if (o < best) best = o;
        }
        if (lane == 0) s_part[w] = best;
        __syncthreads();
        if (t == 0) {
            unsigned long long m = s_part[0];
            #pragma unroll
            for (int i = 1; i < 4; ++i) if (s_part[i] < m) m = s_part[i];
            s_prev = m;
            g_knn[cid*KNB + r] = (int)(m & 0xffffffffull);
        }
        __syncthreads();
        prev = s_prev;
    }
}

// ---------------- gather + fused conv(6->256)+bias -> g_y1 -------------------
__global__ void k_gconv1(const float* __restrict__ p, const float* __restrict__ f,
                         const float* __restrict__ b2) {
    __shared__ float sw[256*6];
    __shared__ float sb[256];
    int t = threadIdx.x;
    #pragma unroll
    for (int i = 0; i < 6; ++i) sw[t*6+i] = g_w21[t*6+i];
    sb[t] = b2[t];
    int m = blockIdx.x*256 + t;
    int b = m >> 15;                       // 32768 positions per batch
    int idx = g_knn[m];
    const float* pp = p + b*NN*3 + idx*3;
    const float* ff = f + b*3*NN + idx;
    float v0 = pp[0], v1 = pp[1], v2 = pp[2];
    float v3 = ff[0], v4 = ff[NN], v5 = ff[2*NN];
    __syncthreads();
    #pragma unroll 8
    for (int c = 0; c < 256; ++c) {
        const float* wr = &sw[c*6];
        float a = sb[c];
        a = fmaf(wr[0], v0, a); a = fmaf(wr[1], v1, a); a = fmaf(wr[2], v2, a);
        a = fmaf(wr[3], v3, a); a = fmaf(wr[4], v4, a); a = fmaf(wr[5], v5, a);
        g_y1[(size_t)c*MTOT + m] = a;
    }
}

// ---------------- per-channel sum / sumsq (one block per channel) ------------
template<int W>
__global__ void k_stats() {
    const float* y = (W == 2) ? g_y1 : (W == 3) ? g_y3 : g_y4;
    int c = blockIdx.x;
    const float4* row = (const float4*)(y + (size_t)c*MTOT);
    float s = 0.f, q = 0.f;
    for (int j = threadIdx.x; j < MTOT/4; j += 256) {
        float4 v = row[j];
        s += v.x + v.y + v.z + v.w;
        q = fmaf(v.x, v.x, q); q = fmaf(v.y, v.y, q);
        q = fmaf(v.z, v.z, q); q = fmaf(v.w, v.w, q);
    }
    #pragma unroll
    for (int off = 16; off; off >>= 1) {
        s += __shfl_down_sync(0xffffffffu, s, off);
        q += __shfl_down_sync(0xffffffffu, q, off);
    }
    __shared__ float ss[8], qq[8];
    int w = threadIdx.x >> 5, lane = threadIdx.x & 31;
    if (lane == 0) { ss[w] = s; qq[w] = q; }
    __syncthreads();
    if (threadIdx.x == 0) {
        float S = 0.f, Q = 0.f;
        #pragma unroll
        for (int i = 0; i < 8; ++i) { S += ss[i]; Q += qq[i]; }
        g_sum[c] = S; g_sq[c] = Q;
    }
}

// ---------------- BN params: scale/shift -------------------------------------
template<int STAGE>
__global__ void k_params(const float* __restrict__ g, const float* __restrict__ be) {
    constexpr int C = (STAGE == 3) ? 512 : 256;
    float* sc = (STAGE == 2) ? g_s2 : (STAGE == 3) ? g_s3 : g_s4;
    float* sh = (STAGE == 2) ? g_t2 : (STAGE == 3) ? g_t3 : g_t4;
    int c = blockIdx.x*blockDim.x + threadIdx.x;
    if (c < C) {
        const float inv = 1.0f / (float)MTOT;
        float mean = g_sum[c]*inv;
        float var  = fmaf(-mean, mean, g_sq[c]*inv);
        float r    = rsqrtf(var + 1e-5f);
        float s    = g[c]*r;
        sc[c] = s;
        sh[c] = fmaf(-mean, s, be[c]);
    }
}

// ---------------- xm = max_k relu(affine2(y1)) -------------------------------
__global__ void k_xm() {
    int gid = blockIdx.x*256 + threadIdx.x;   // 256*4096 threads
    int c = gid >> 12, bs = gid & 4095;
    float s = g_s2[c], h = g_t2[c];
    const float4* r = (const float4*)(g_y1 + (size_t)c*MTOT + bs*KNB);
    float mx = 0.f;
    #pragma unroll
    for (int j = 0; j < 8; ++j) {
        float4 v = r[j];
        mx = fmaxf(mx, fmaf(v.x, s, h)); mx = fmaxf(mx, fmaf(v.y, s, h));
        mx = fmaxf(mx, fmaf(v.z, s, h)); mx = fmaxf(mx, fmaf(v.w, s, h));
    }
    g_xm[c*(BB*NSAMP) + bs] = mx;
}

// ---------------- fp32 GEMM (FFMA2), 128x128x16 tiles, 8x8/thread ------------
// MODE 0: h3   = w3[:, :256]  @ xm                       (Nn=4096,   Kd=256)
// MODE 1: y3   = w3[:, 256:]  @ relu(aff2(y1)) + h3      (Nn=131072, Kd=256)
// MODE 2: y4   = w4           @ relu(aff3(y3))           (Nn=131072, Kd=512)
template<int MODE>
__global__ void __launch_bounds__(256, 2) k_gemm(const float* __restrict__ A) {
    constexpr int Nn  = (MODE == 0) ? (BB*NSAMP) : MTOT;
    constexpr int Kd  = (MODE == 2) ? 512 : 256;
    constexpr int lda = 512;
    const float* __restrict__ Bm = (MODE == 0) ? g_xm : (MODE == 1) ? g_y1 : g_y3;
    float* __restrict__ C        = (MODE == 0) ? g_h3 : (MODE == 1) ? g_y3 : g_y4;
    const float* __restrict__ bsc = (MODE == 1) ? g_s2 : g_s3;
    const float* __restrict__ bsh = (MODE == 1) ? g_t2 : g_t3;

    __shared__ unsigned long long As[16][128];   // A value duplicated into both f32x2 halves
    __shared__ float Bs[16][128];

    int m0 = blockIdx.x * 128;
    int n0 = blockIdx.y * 128;
    int t  = threadIdx.x;
    int ar  = t & 127, akq = (t >> 7) * 8;       // A: 128 rows x 16 k, 8 floats/thread
    int bkr = t >> 4,  bnc = (t & 15) * 8;       // B: 16 k x 128 n, 8 floats/thread
    int ty = t >> 4, tx = t & 15;                // output 8x8 tile

    unsigned long long acc[8][4];
    #pragma unroll
    for (int i = 0; i < 8; ++i)
        #pragma unroll
        for (int j = 0; j < 4; ++j) acc[i][j] = 0ull;

    for (int k0 = 0; k0 < Kd; k0 += 16) {
        const float* ga = A + (size_t)(m0 + ar)*lda + k0 + akq;
        float4 a0 = *(const float4*)ga;
        float4 a1 = *(const float4*)(ga + 4);
        const float* gb = Bm + (size_t)(k0 + bkr)*Nn + n0 + bnc;
        float4 b0 = *(const float4*)gb;
        float4 b1 = *(const float4*)(gb + 4);
        if (MODE != 0) {
            float s = bsc[k0 + bkr], h = bsh[k0 + bkr];
            b0.x = fmaxf(fmaf(b0.x, s, h), 0.f); b0.y = fmaxf(fmaf(b0.y, s, h), 0.f);
            b0.z = fmaxf(fmaf(b0.z, s, h), 0.f); b0.w = fmaxf(fmaf(b0.w, s, h), 0.f);
            b1.x = fmaxf(fmaf(b1.x, s, h), 0.f); b1.y = fmaxf(fmaf(b1.y, s, h), 0.f);
            b1.z = fmaxf(fmaf(b1.z, s, h), 0.f); b1.w = fmaxf(fmaf(b1.w, s, h), 0.f);
        }
        __syncthreads();
        As[akq+0][ar] = dup2(a0.x); As[akq+1][ar] = dup2(a0.y);
        As[akq+2][ar] = dup2(a0.z); As[akq+3][ar] = dup2(a0.w);
        As[akq+4][ar] = dup2(a1.x); As[akq+5][ar] = dup2(a1.y);
        As[akq+6][ar] = dup2(a1.z); As[akq+7][ar] = dup2(a1.w);
        *(float4*)&Bs[bkr][bnc]     = b0;
        *(float4*)&Bs[bkr][bnc + 4] = b1;
        __syncthreads();
        #pragma unroll
        for (int kk = 0; kk < 16; ++kk) {
            unsigned long long af[8], bf[4];
            const unsigned long long* ap = &As[kk][ty*8];
            #pragma unroll
            for (int i = 0; i < 8; ++i) af[i] = ap[i];
            const unsigned long long* bp = (const unsigned long long*)&Bs[kk][tx*8];
            #pragma unroll
            for (int j = 0; j < 4; ++j) bf[j] = bp[j];
            #pragma unroll
            for (int i = 0; i < 8; ++i)
                #pragma unroll
                for (int j = 0; j < 4; ++j)
                    asm("fma.rn.f32x2 %0, %1, %2, %0;"
                        : "+l"(acc[i][j]) : "l"(af[i]), "l"(bf[j]));
        }
    }

    constexpr int ng5 = Nn >> 5;
    #pragma unroll
    for (int i = 0; i < 8; ++i) {
        int gr = m0 + ty*8 + i;
        float out[8];
        #pragma unroll
        for (int j = 0; j < 4; ++j) {
            out[2*j]   = __uint_as_float((unsigned int)(acc[i][j] & 0xffffffffull));
            out[2*j+1] = __uint_as_float((unsigned int)(acc[i][j] >> 32));
        }
        if (MODE == 1) {
            #pragma unroll
            for (int j = 0; j < 8; ++j)
                out[j] += g_h3[(size_t)gr*ng5 + ((n0 + tx*8 + j) >> 5)];
        }
        float4* cp = (float4*)(C + (size_t)gr*Nn + n0 + tx*8);
        cp[0] = make_float4(out[0], out[1], out[2], out[3]);
        cp[1] = make_float4(out[4], out[5], out[6], out[7]);
    }
}

// ---------------- final: out_feat = max_k relu(affine4(y4)) ------------------
__global__ void k_final(float* __restrict__ out) {
    int gid = blockIdx.x*256 + threadIdx.x;   // 256*4096
    int c = gid >> 12, bs = gid & 4095;
    int b = bs >> 10, s = bs & 1023;
    float sc = g_s4[c], h = g_t4[c];
    const float4* r = (const float4*)(g_y4 + (size_t)c*MTOT + bs*KNB);
    float mx = 0.f;
    #pragma unroll
    for (int j = 0; j < 8; ++j) {
        float4 v = r[j];
        mx = fmaxf(mx, fmaf(v.x, sc, h)); mx = fmaxf(mx, fmaf(v.y, sc, h));
        mx = fmaxf(mx, fmaf(v.z, sc, h)); mx = fmaxf(mx, fmaf(v.w, sc, h));
    }
    out[(((b << 8) + c) << 10) + s] = mx;
}

// ---------------- launcher ---------------------------------------------------
extern "C" void kernel_launch(void* const* d_in, const int* in_sizes, int n_in,
                              void* d_out, int out_size) {
    const float* p   = (const float*)d_in[0];
    const float* f   = (const float*)d_in[1];
    const float* w1  = (const float*)d_in[2];
    const float* w2  = (const float*)d_in[3];
    const float* b2  = (const float*)d_in[4];
    const float* g2  = (const float*)d_in[5];
    const float* be2 = (const float*)d_in[6];
    const float* w3  = (const float*)d_in[7];
    const float* g3  = (const float*)d_in[8];
    const float* be3 = (const float*)d_in[9];
    const float* w4  = (const float*)d_in[10];
    const float* g4  = (const float*)d_in[11];
    const float* be4 = (const float*)d_in[12];
    float* out = (float*)d_out;

    k_w21<<<1, 256>>>(w1, w2);
    k_fps<<<BB, 1024>>>(p, out);                      // writes cntrd into d_out[0..12288)
    k_knn<<<BB*NSAMP, 128>>>(p, out);
    k_gconv1<<<MTOT/256, 256>>>(p, f, b2);
    k_stats<2><<<256, 256>>>();
    k_params<2><<<2, 256>>>(g2, be2);
    k_xm<<<4096, 256>>>();
    k_gemm<0><<<dim3(4, (BB*NSAMP)/128), 256>>>(w3);        // h3 = w3a @ xm
    k_gemm<1><<<dim3(4, MTOT/128), 256>>>(w3 + 256);        // y3 = w3b @ x + h3
    k_stats<3><<<512, 256>>>();
    k_params<3><<<2, 256>>>(g3, be3);
    k_gemm<2><<<dim3(2, MTOT/128), 256>>>(w4);              // y4 = w4 @ x3
    k_stats<4><<<256, 256>>>();
    k_params<4><<<2, 256>>>(g4, be4);
    k_final<<<4096, 256>>>(out + BB*NSAMP*3);
}

// round 6
// speedup vs baseline: 1.4837x; 1.4837x over previous
#include <cuda_runtime.h>
#include <cuda_fp16.h>
#include <cstdint>

#define BB 4
#define NN 4096
#define NSAMP 1024
#define KNB 32
#define MTOT (BB*NSAMP*KNB)   // 131072 positions

// ---------------- scratch (device globals; no allocations allowed) ------------
__device__ float g_w21[256*6];
__device__ int   g_knn[MTOT];
__device__ float g_y1[(size_t)MTOT*256];       // conv1 out, [m][c] fp32
__device__ __half g_y1h[(size_t)MTOT*256];     // relu(aff2(y1)) hi, [m][c]
__device__ __half g_y1l[(size_t)MTOT*256];     // lo
__device__ float g_xm[256*BB*NSAMP];           // [c][bs]
__device__ float g_h3[512*BB*NSAMP];           // [row][bs]
__device__ float g_y3[(size_t)MTOT*512];       // conv3 out, [n][512] fp32
__device__ __half g_y3h[(size_t)MTOT*512];
__device__ __half g_y3l[(size_t)MTOT*512];
__device__ float g_y4[(size_t)MTOT*256];       // conv4 out, [n][256] fp32
__device__ __half g_w3bh[512*256], g_w3bl[512*256];
__device__ __half g_w4h[256*512],  g_w4l[256*512];
__device__ float g_sum2[256], g_sq2[256];
__device__ float g_sum3[512], g_sq3[512];
__device__ float g_sum4[256], g_sq4[256];
__device__ float g_s2[256], g_t2[256];
__device__ float g_s3[512], g_t3[512];
__device__ float g_s4[256], g_t4[256];

// ---------------- helpers -----------------------------------------------------
__device__ __forceinline__ uint32_t smem_to_u32(const void* p) {
    uint32_t a;
    asm("{ .reg .u64 t; cvta.to.shared.u64 t, %1; cvt.u32.u64 %0, t; }" : "=r"(a) : "l"(p));
    return a;
}
__device__ __forceinline__ unsigned long long dup2(float a) {
    unsigned int u = __float_as_uint(a);
    return ((unsigned long long)u << 32) | (unsigned long long)u;
}
__device__ __forceinline__ unsigned int fmono(float f) {
    unsigned int u = __float_as_uint(f);
    return (u & 0x80000000u) ? ~u : (u | 0x80000000u);
}
__device__ __forceinline__ uint32_t pk2h(__half a, __half b) {
    return ((uint32_t)__half_as_ushort(b) << 16) | (uint32_t)__half_as_ushort(a);
}

#define CP_ASYNC16(dst, src) \
    asm volatile("cp.async.cg.shared.global [%0], [%1], 16;" :: "r"(dst), "l"(src) : "memory")
#define CP_COMMIT() asm volatile("cp.async.commit_group;" ::: "memory")
#define CP_WAIT0() asm volatile("cp.async.wait_group 0;" ::: "memory")
#define CP_WAIT1() asm volatile("cp.async.wait_group 1;" ::: "memory")

__device__ __forceinline__ void ldsm_x4(uint32_t& r0, uint32_t& r1, uint32_t& r2, uint32_t& r3, uint32_t addr) {
    asm volatile("ldmatrix.sync.aligned.m8n8.x4.shared.b16 {%0,%1,%2,%3}, [%4];"
        : "=r"(r0), "=r"(r1), "=r"(r2), "=r"(r3) : "r"(addr));
}
__device__ __forceinline__ void ldsm_x2(uint32_t& r0, uint32_t& r1, uint32_t addr) {
    asm volatile("ldmatrix.sync.aligned.m8n8.x2.shared.b16 {%0,%1}, [%2];"
        : "=r"(r0), "=r"(r1) : "r"(addr));
}
__device__ __forceinline__ void mma16816(float* d, const uint32_t* a, const uint32_t* b) {
    asm volatile("mma.sync.aligned.m16n8k16.row.col.f32.f16.f16.f32 "
        "{%0,%1,%2,%3}, {%4,%5,%6,%7}, {%8,%9}, {%0,%1,%2,%3};"
        : "+f"(d[0]), "+f"(d[1]), "+f"(d[2]), "+f"(d[3])
        : "r"(a[0]), "r"(a[1]), "r"(a[2]), "r"(a[3]), "r"(b[0]), "r"(b[1]));
}

// ---------------- zero stats --------------------------------------------------
__global__ void k_zero() {
    int t = threadIdx.x;  // 512
    if (t < 256) { g_sum2[t]=0.f; g_sq2[t]=0.f; g_sum4[t]=0.f; g_sq4[t]=0.f; }
    g_sum3[t]=0.f; g_sq3[t]=0.f;
}

// ---------------- w21 = w2 @ w1 -----------------------------------------------
__global__ void k_w21(const float* __restrict__ w1, const float* __restrict__ w2) {
    int o = threadIdx.x;
    float acc[6] = {0.f,0.f,0.f,0.f,0.f,0.f};
    for (int c = 0; c < 256; ++c) {
        float w = w2[o*256 + c];
        #pragma unroll
        for (int i = 0; i < 6; ++i) acc[i] = fmaf(w, w1[c*6+i], acc[i]);
    }
    #pragma unroll
    for (int i = 0; i < 6; ++i) g_w21[o*6+i] = acc[i];
}

// ---------------- weight fp16 hi/lo split -------------------------------------
__global__ void k_wsplit(const float* __restrict__ w3, const float* __restrict__ w4) {
    int i = blockIdx.x*256 + threadIdx.x;   // 0..131071
    int r = i >> 8, c = i & 255;
    float v = w3[r*512 + 256 + c];
    __half h = __float2half(v);
    g_w3bh[i] = h; g_w3bl[i] = __float2half(v - __half2float(h));
    float u = w4[i];
    __half h2 = __float2half(u);
    g_w4h[i] = h2; g_w4l[i] = __float2half(u - __half2float(h2));
}

// ---------------- FPS ---------------------------------------------------------
__global__ void k_fps(const float* __restrict__ p, float* __restrict__ outC) {
    int b = blockIdx.x;
    const float* pb = p + b*NN*3;
    int t = threadIdx.x;
    float px[4], py[4], pz[4], dm[4];
    #pragma unroll
    for (int j = 0; j < 4; ++j) {
        int i = t + j*1024;
        px[j] = pb[i*3]; py[j] = pb[i*3+1]; pz[j] = pb[i*3+2];
        dm[j] = 1e10f;
    }
    __shared__ float s_c[3];
    __shared__ float s_v[32];
    __shared__ int   s_i[32];
    __shared__ int   s_far;
    int far = 0;
    int lane = t & 31, w = t >> 5;
    for (int it = 0; it < NSAMP; ++it) {
        if (t == 0) {
            float cx = pb[far*3], cy = pb[far*3+1], cz = pb[far*3+2];
            s_c[0] = cx; s_c[1] = cy; s_c[2] = cz;
            float* o = outC + (b*NSAMP + it)*3;
            o[0] = cx; o[1] = cy; o[2] = cz;
        }
        __syncthreads();
        float cx = s_c[0], cy = s_c[1], cz = s_c[2];
        float best = -1.0f; int bi = 0;
        #pragma unroll
        for (int j = 0; j < 4; ++j) {
            float dx = px[j]-cx, dy = py[j]-cy, dz = pz[j]-cz;
            float d  = fmaf(dz, dz, fmaf(dy, dy, dx*dx));
            float nd = fminf(dm[j], d);
            dm[j] = nd;
            if (nd > best) { best = nd; bi = t + j*1024; }
        }
        #pragma unroll
        for (int off = 16; off; off >>= 1) {
            float ov = __shfl_down_sync(0xffffffffu, best, off);
            int   oi = __shfl_down_sync(0xffffffffu, bi,   off);
            if (ov > best || (ov == best && oi < bi)) { best = ov; bi = oi; }
        }
        if (lane == 0) { s_v[w] = best; s_i[w] = bi; }
        __syncthreads();
        if (w == 0) {
            best = s_v[lane]; bi = s_i[lane];
            #pragma unroll
            for (int off = 16; off; off >>= 1) {
                float ov = __shfl_down_sync(0xffffffffu, best, off);
                int   oi = __shfl_down_sync(0xffffffffu, bi,   off);
                if (ov > best || (ov == best && oi < bi)) { best = ov; bi = oi; }
            }
            if (lane == 0) s_far = bi;
        }
        __syncthreads();
        far = s_far;
    }
}

// ---------------- KNN ---------------------------------------------------------
__global__ void k_knn(const float* __restrict__ p, const float* __restrict__ cent) {
    int cid = blockIdx.x;
    int b = cid >> 10;
    const float* pb = p + b*NN*3;
    int t = threadIdx.x;  // 128
    float cx = cent[cid*3], cy = cent[cid*3+1], cz = cent[cid*3+2];
    float cn = cx*cx + cy*cy + cz*cz;
    unsigned long long key[32];
    #pragma unroll
    for (int j = 0; j < 32; ++j) {
        int i = j*128 + t;
        float x = pb[i*3], y = pb[i*3+1], z = pb[i*3+2];
        float pn = x*x + y*y + z*z;
        float dot = fmaf(cx, x, fmaf(cy, y, cz*z));
        float d2  = fmaf(-2.0f, dot, cn + pn);
        key[j] = ((unsigned long long)fmono(d2) << 32) | (unsigned int)i;
    }
    __shared__ unsigned long long s_part[4];
    __shared__ unsigned long long s_prev;
    unsigned long long prev = 0ull;
    int w = t >> 5, lane = t & 31;
    for (int r = 0; r < KNB; ++r) {
        unsigned long long best = ~0ull;
        #pragma unroll
        for (int j = 0; j < 32; ++j) {
            unsigned long long k = key[j];
            if (k > prev && k < best) best = k;
        }
        #pragma unroll
        for (int off = 16; off; off >>= 1) {
            unsigned long long o = __shfl_down_sync(0xffffffffu, best, off);
            if (o < best) best = o;
        }
        if (lane == 0) s_part[w] = best;
        __syncthreads();
        if (t == 0) {
            unsigned long long m = s_part[0];
            #pragma unroll
            for (int i = 1; i < 4; ++i) if (s_part[i] < m) m = s_part[i];
            s_prev = m;
            g_knn[cid*KNB + r] = (int)(m & 0xffffffffull);
        }
        __syncthreads();
        prev = s_prev;
    }
}

// ------- gather + conv(6->256)+bias -> y1 [m][256] + stage-2 stats ------------
__global__ void k_gconv1(const float* __restrict__ p, const float* __restrict__ f,
                         const float* __restrict__ b2) {
    __shared__ float sw[256*6];
    __shared__ float sbb[256];
    __shared__ float sv[64][6];
    int t = threadIdx.x;
    #pragma unroll
    for (int i = 0; i < 6; ++i) sw[t*6+i] = g_w21[t*6+i];
    sbb[t] = b2[t];
    int m0 = blockIdx.x*64;
    if (t < 64) {
        int m = m0 + t;
        int b = m >> 15;
        int idx = g_knn[m];
        const float* pp = p + b*NN*3 + idx*3;
        const float* ff = f + b*3*NN + idx;
        sv[t][0] = pp[0]; sv[t][1] = pp[1]; sv[t][2] = pp[2];
        sv[t][3] = ff[0]; sv[t][4] = ff[NN]; sv[t][5] = ff[2*NN];
    }
    __syncthreads();
    int c = t;
    float w0 = sw[c*6], w1 = sw[c*6+1], w2 = sw[c*6+2];
    float w3 = sw[c*6+3], w4 = sw[c*6+4], w5 = sw[c*6+5];
    float bias = sbb[c];
    float s = 0.f, q = 0.f;
    #pragma unroll 4
    for (int pp = 0; pp < 64; ++pp) {
        float a = bias;
        a = fmaf(w0, sv[pp][0], a); a = fmaf(w1, sv[pp][1], a); a = fmaf(w2, sv[pp][2], a);
        a = fmaf(w3, sv[pp][3], a); a = fmaf(w4, sv[pp][4], a); a = fmaf(w5, sv[pp][5], a);
        g_y1[(size_t)(m0+pp)*256 + c] = a;
        s += a; q = fmaf(a, a, q);
    }
    atomicAdd(&g_sum2[c], s);
    atomicAdd(&g_sq2[c], q);
}

// ---------------- BN params ---------------------------------------------------
template<int STAGE>
__global__ void k_params(const float* __restrict__ g, const float* __restrict__ be) {
    constexpr int C = (STAGE == 3) ? 512 : 256;
    const float* su = (STAGE == 2) ? g_sum2 : (STAGE == 3) ? g_sum3 : g_sum4;
    const float* sq = (STAGE == 2) ? g_sq2  : (STAGE == 3) ? g_sq3  : g_sq4;
    float* sc = (STAGE == 2) ? g_s2 : (STAGE == 3) ? g_s3 : g_s4;
    float* sh = (STAGE == 2) ? g_t2 : (STAGE == 3) ? g_t3 : g_t4;
    int c = blockIdx.x*blockDim.x + threadIdx.x;
    if (c < C) {
        const float inv = 1.0f / (float)MTOT;
        float mean = su[c]*inv;
        float var  = fmaf(-mean, mean, sq[c]*inv);
        float r    = rsqrtf(var + 1e-5f);
        float s    = g[c]*r;
        sc[c] = s;
        sh[c] = fmaf(-mean, s, be[c]);
    }
}

// ---- c1: relu(aff2(y1)) -> fp16 hi/lo [m][256] + xm [c][bs] ------------------
__global__ void k_c1() {
    int bs = blockIdx.x;      // 4096
    int c  = threadIdx.x;     // 256
    float sc = g_s2[c], hh = g_t2[c];
    size_t base = (size_t)bs*32*256 + c;
    float mx = 0.f;
    #pragma unroll 8
    for (int pp = 0; pp < 32; ++pp) {
        float v = g_y1[base + (size_t)pp*256];
        float a = fmaxf(fmaf(v, sc, hh), 0.f);
        mx = fmaxf(mx, a);
        __half h = __float2half(a);
        g_y1h[base + (size_t)pp*256] = h;
        g_y1l[base + (size_t)pp*256] = __float2half(a - __half2float(h));
    }
    g_xm[c*(BB*NSAMP) + bs] = mx;
}

// ---- c3: relu(aff3(y3)) -> fp16 hi/lo [n][512] -------------------------------
__global__ void k_c3() {
    size_t i = (size_t)blockIdx.x*256 + threadIdx.x;   // float4 index (16.7M)
    float4 v = ((const float4*)g_y3)[i];
    int k = ((int)(i & 127)) * 4;
    float a0 = fmaxf(fmaf(v.x, g_s3[k],   g_t3[k]),   0.f);
    float a1 = fmaxf(fmaf(v.y, g_s3[k+1], g_t3[k+1]), 0.f);
    float a2 = fmaxf(fmaf(v.z, g_s3[k+2], g_t3[k+2]), 0.f);
    float a3 = fmaxf(fmaf(v.w, g_s3[k+3], g_t3[k+3]), 0.f);
    __half h0 = __float2half(a0), h1 = __float2half(a1);
    __half h2 = __float2half(a2), h3 = __float2half(a3);
    __half l0 = __float2half(a0 - __half2float(h0));
    __half l1 = __float2half(a1 - __half2float(h1));
    __half l2 = __float2half(a2 - __half2float(h2));
    __half l3 = __float2half(a3 - __half2float(h3));
    ((uint2*)g_y3h)[i] = make_uint2(pk2h(h0,h1), pk2h(h2,h3));
    ((uint2*)g_y3l)[i] = make_uint2(pk2h(l0,l1), pk2h(l2,l3));
}

// ---------------- small fp32 GEMM: h3 = w3[:, :256] @ xm ----------------------
__global__ void __launch_bounds__(256, 2) k_gemm0(const float* __restrict__ A) {
    constexpr int Nn = BB*NSAMP;     // 4096
    constexpr int Kd = 256, lda = 512;
    __shared__ unsigned long long As[16][128];
    __shared__ float Bs[16][128];
    int m0 = blockIdx.x * 128;
    int n0 = blockIdx.y * 128;
    int t  = threadIdx.x;
    int ar  = t & 127, akq = (t >> 7) * 8;
    int bkr = t >> 4,  bnc = (t & 15) * 8;
    int ty = t >> 4, tx = t & 15;
    unsigned long long acc[8][4];
    #pragma unroll
    for (int i = 0; i < 8; ++i)
        #pragma unroll
        for (int j = 0; j < 4; ++j) acc[i][j] = 0ull;
    for (int k0 = 0; k0 < Kd; k0 += 16) {
        const float* ga = A + (size_t)(m0 + ar)*lda + k0 + akq;
        float4 a0 = *(const float4*)ga;
        float4 a1 = *(const float4*)(ga + 4);
        const float* gb = g_xm + (size_t)(k0 + bkr)*Nn + n0 + bnc;
        float4 b0 = *(const float4*)gb;
        float4 b1 = *(const float4*)(gb + 4);
        __syncthreads();
        As[akq+0][ar] = dup2(a0.x); As[akq+1][ar] = dup2(a0.y);
        As[akq+2][ar] = dup2(a0.z); As[akq+3][ar] = dup2(a0.w);
        As[akq+4][ar] = dup2(a1.x); As[akq+5][ar] = dup2(a1.y);
        As[akq+6][ar] = dup2(a1.z); As[akq+7][ar] = dup2(a1.w);
        *(float4*)&Bs[bkr][bnc]     = b0;
        *(float4*)&Bs[bkr][bnc + 4] = b1;
        __syncthreads();
        #pragma unroll
        for (int kk = 0; kk < 16; ++kk) {
            unsigned long long af[8], bf[4];
            const unsigned long long* ap = &As[kk][ty*8];
            #pragma unroll
            for (int i = 0; i < 8; ++i) af[i] = ap[i];
            const unsigned long long* bp = (const unsigned long long*)&Bs[kk][tx*8];
            #pragma unroll
            for (int j = 0; j < 4; ++j) bf[j] = bp[j];
            #pragma unroll
            for (int i = 0; i < 8; ++i)
                #pragma unroll
                for (int j = 0; j < 4; ++j)
                    asm("fma.rn.f32x2 %0, %1, %2, %0;"
                        : "+l"(acc[i][j]) : "l"(af[i]), "l"(bf[j]));
        }
    }
    #pragma unroll
    for (int i = 0; i < 8; ++i) {
        int gr = m0 + ty*8 + i;
        float out[8];
        #pragma unroll
        for (int j = 0; j < 4; ++j) {
            out[2*j]   = __uint_as_float((unsigned int)(acc[i][j] & 0xffffffffull));
            out[2*j+1] = __uint_as_float((unsigned int)(acc[i][j] >> 32));
        }
        float4* cp = (float4*)(g_h3 + (size_t)gr*Nn + n0 + tx*8);
        cp[0] = make_float4(out[0], out[1], out[2], out[3]);
        cp[1] = make_float4(out[4], out[5], out[6], out[7]);
    }
}

// ---------------- mma.sync fp16 hi/lo GEMM ------------------------------------
// MODE 1: y3[n][512] = w3b(512x256) @ x1^T  + h3-broadcast, stats3
// MODE 2: y4[n][256] = w4 (256x512) @ x3^T,                 stats4
// CTA 128x128, 8 warps (2x4), warp tile 64x32, K-chunk 32, 3-stage cp.async.
// Smem row stride 80B (8-row ldmatrix stride hits 8 distinct 16B banks).
#define STG_BYTES 40960                 // Ah(10240)+Al+Bh+Bl per stage
#define MMA_SMEM  (3*STG_BYTES)

template<int MODE>
__device__ __forceinline__ void mma_issue(uint32_t sbase, int st, int k0,
                                          int m0c, int n0c, int tid) {
    constexpr int Kd = (MODE == 1) ? 256 : 512;
    const __half* __restrict__ Ah = (MODE == 1) ? g_w3bh : g_w4h;
    const __half* __restrict__ Al = (MODE == 1) ? g_w3bl : g_w4l;
    const __half* __restrict__ Bh = (MODE == 1) ? g_y1h : g_y3h;
    const __half* __restrict__ Bl = (MODE == 1) ? g_y1l : g_y3l;
    uint32_t base = sbase + st*STG_BYTES;
    #pragma unroll
    for (int i = 0; i < 4; ++i) {
        int u = tid + i*256;              // 0..1023
        int hl = u >> 9;
        int r = (u >> 2) & 127;
        int q = u & 3;
        const __half* src = (hl ? Al : Ah) + (size_t)(m0c + r)*Kd + k0 + q*8;
        CP_ASYNC16(base + hl*10240 + r*80 + q*16, src);
    }
    #pragma unroll
    for (int i = 0; i < 4; ++i) {
        int u = tid + i*256;
        int hl = u >> 9;
        int r = (u >> 2) & 127;
        int q = u & 3;
        const __half* src = (hl ? Bl : Bh) + (size_t)(n0c + r)*Kd + k0 + q*8;
        CP_ASYNC16(base + 20480 + hl*10240 + r*80 + q*16, src);
    }
}

template<int MODE>
__global__ void __launch_bounds__(256) k_mma() {
    constexpr int Kd = (MODE == 1) ? 256 : 512;
    constexpr int KT = Kd / 32;
    constexpr int Ms = (MODE == 1) ? 512 : 256;    // C row stride
    float* __restrict__ C  = (MODE == 1) ? g_y3 : g_y4;
    float* __restrict__ Su = (MODE == 1) ? g_sum3 : g_sum4;
    float* __restrict__ Sq = (MODE == 1) ? g_sq3 : g_sq4;

    extern __shared__ char smem[];
    uint32_t sb = smem_to_u32(smem);
    int tid = threadIdx.x, lane = tid & 31, wid = tid >> 5;
    int wm = wid >> 2, wn = wid & 3;
    int m0c = blockIdx.x * 128, n0c = blockIdx.y * 128;

    float acc[4][4][4];
    #pragma unroll
    for (int a = 0; a < 4; ++a)
        #pragma unroll
        for (int b = 0; b < 4; ++b)
            #pragma unroll
            for (int c = 0; c < 4; ++c) acc[a][b][c] = 0.f;

    // ldmatrix per-thread address components
    int sel = lane >> 3;
    uint32_t aRow = (uint32_t)((sel & 1)*8 + (lane & 7));
    uint32_t aCol = (uint32_t)((sel >> 1) * 16);
    uint32_t bRow = (uint32_t)(wn*32 + (lane & 7));
    uint32_t bCol = (uint32_t)(((lane >> 3) & 1) * 16);

    mma_issue<MODE>(sb, 0, 0,  m0c, n0c, tid); CP_COMMIT();
    mma_issue<MODE>(sb, 1, 32, m0c, n0c, tid); CP_COMMIT();

    for (int kt = 0; kt < KT; ++kt) {
        if (kt == KT-1) { CP_WAIT0(); } else { CP_WAIT1(); }
        __syncthreads();
        if (kt + 2 < KT) {
            mma_issue<MODE>(sb, (kt+2)%3, (kt+2)*32, m0c, n0c, tid);
            CP_COMMIT();
        }
        uint32_t sA = sb + (kt%3)*STG_BYTES;
        uint32_t sB = sA + 20480;
        #pragma unroll
        for (int ks = 0; ks < 2; ++ks) {
            uint32_t kOff = (uint32_t)(ks*32);
            uint32_t af[4][4], bf[4][2];
            // pass 1: Ah x Bh
            #pragma unroll
            for (int mt = 0; mt < 4; ++mt)
                ldsm_x4(af[mt][0], af[mt][1], af[mt][2], af[mt][3],
                        sA + (uint32_t)(wm*64 + mt*16 + aRow)*80 + kOff + aCol);
            #pragma unroll
            for (int nt = 0; nt < 4; ++nt)
                ldsm_x2(bf[nt][0], bf[nt][1],
                        sB + (bRow + (uint32_t)(nt*8))*80 + kOff + bCol);
            #pragma unroll
            for (int mt = 0; mt < 4; ++mt)
                #pragma unroll
                for (int nt = 0; nt < 4; ++nt)
                    mma16816(acc[mt][nt], af[mt], bf[nt]);
            // pass 2: Ah x Bl
            #pragma unroll
            for (int nt = 0; nt < 4; ++nt)
                ldsm_x2(bf[nt][0], bf[nt][1],
                        sB + 10240 + (bRow + (uint32_t)(nt*8))*80 + kOff + bCol);
            #pragma unroll
            for (int mt = 0; mt < 4; ++mt)
                #pragma unroll
                for (int nt = 0; nt < 4; ++nt)
                    mma16816(acc[mt][nt], af[mt], bf[nt]);
            // pass 3: Al x Bh
            #pragma unroll
            for (int mt = 0; mt < 4; ++mt)
                ldsm_x4(af[mt][0], af[mt][1], af[mt][2], af[mt][3],
                        sA + 10240 + (uint32_t)(wm*64 + mt*16 + aRow)*80 + kOff + aCol);
            #pragma unroll
            for (int nt = 0; nt < 4; ++nt)
                ldsm_x2(bf[nt][0], bf[nt][1],
                        sB + (bRow + (uint32_t)(nt*8))*80 + kOff + bCol);
            #pragma unroll
            for (int mt = 0; mt < 4; ++mt)
                #pragma unroll
                for (int nt = 0; nt < 4; ++nt)
                    mma16816(acc[mt][nt], af[mt], bf[nt]);
        }
    }

    // ---------------- epilogue: store C (+h3), fused BN stats ----------------
    __syncthreads();                       // smem reuse for reduction
    float* redS = (float*)smem;            // [128][16]
    float* redQ = (float*)(smem + 8192);
    int qrow = lane >> 2, qcol = lane & 3;

    #pragma unroll
    for (int mt = 0; mt < 4; ++mt) {
        #pragma unroll
        for (int hf = 0; hf < 2; ++hf) {
            int mloc = wm*64 + mt*16 + hf*8 + qrow;
            int mg = m0c + mloc;
            float h3v = 0.f;
            if (MODE == 1) h3v = g_h3[(size_t)mg*(BB*NSAMP) + (n0c >> 5) + wn];
            float s = 0.f, q = 0.f;
            #pragma unroll
            for (int nt = 0; nt < 4; ++nt) {
                #pragma unroll
                for (int j = 0; j < 2; ++j) {
                    float v = acc[mt][nt][hf*2 + j] + h3v;
                    int ng = n0c + wn*32 + nt*8 + qcol*2 + j;
                    C[(size_t)ng*Ms + mg] = v;
                    s += v; q = fmaf(v, v, q);
                }
            }
            redS[mloc*16 + wn*4 + qcol] = s;
            redQ[mloc*16 + wn*4 + qcol] = q;
        }
    }
    __syncthreads();
    if (tid < 128) {
        float s = 0.f;
        #pragma unroll
        for (int i = 0; i < 16; ++i) s += redS[tid*16 + i];
        atomicAdd(&Su[m0c + tid], s);
    } else {
        int m = tid - 128;
        float q = 0.f;
        #pragma unroll
        for (int i = 0; i < 16; ++i) q += redQ[m*16 + i];
        atomicAdd(&Sq[m0c + m], q);
    }
}

// ---------------- final: out_feat = max_k relu(aff4(y4)) ----------------------
__global__ void k_final(float* __restrict__ out) {
    int bs = blockIdx.x;   // 4096
    int c  = threadIdx.x;  // 256
    float sc = g_s4[c], hh = g_t4[c];
    size_t base = (size_t)bs*32*256 + c;
    float mx = 0.f;
    #pragma unroll 8
    for (int pp = 0; pp < 32; ++pp) {
        float v = g_y4[base + (size_t)pp*256];
        mx = fmaxf(mx, fmaxf(fmaf(v, sc, hh), 0.f));
    }
    int b = bs >> 10, sI = bs & 1023;
    out[(((b << 8) + c) << 10) + sI] = mx;
}

// ---------------- launcher ----------------------------------------------------
extern "C" void kernel_launch(void* const* d_in, const int* in_sizes, int n_in,
                              void* d_out, int out_size) {
    const float* p   = (const float*)d_in[0];
    const float* f   = (const float*)d_in[1];
    const float* w1  = (const float*)d_in[2];
    const float* w2  = (const float*)d_in[3];
    const float* b2  = (const float*)d_in[4];
    const float* g2  = (const float*)d_in[5];
    const float* be2 = (const float*)d_in[6];
    const float* w3  = (const float*)d_in[7];
    const float* g3  = (const float*)d_in[8];
    const float* be3 = (const float*)d_in[9];
    const float* w4  = (const float*)d_in[10];
    const float* g4  = (const float*)d_in[11];
    const float* be4 = (const float*)d_in[12];
    float* out = (float*)d_out;

    cudaFuncSetAttribute(k_mma<1>, cudaFuncAttributeMaxDynamicSharedMemorySize, MMA_SMEM);
    cudaFuncSetAttribute(k_mma<2>, cudaFuncAttributeMaxDynamicSharedMemorySize, MMA_SMEM);

    k_zero<<<1, 512>>>();
    k_w21<<<1, 256>>>(w1, w2);
    k_wsplit<<<512, 256>>>(w3, w4);
    k_fps<<<BB, 1024>>>(p, out);                       // cntrd -> d_out[0..12288)
    k_knn<<<BB*NSAMP, 128>>>(p, out);
    k_gconv1<<<MTOT/64, 256>>>(p, f, b2);              // y1 + stats2
    k_params<2><<<2, 256>>>(g2, be2);
    k_c1<<<BB*NSAMP, 256>>>();                         // y1 hi/lo + xm
    k_gemm0<<<dim3(4, 32), 256>>>(w3);                 // h3 = w3a @ xm
    k_mma<1><<<dim3(4, 1024), 256, MMA_SMEM>>>();      // y3 + stats3
    k_params<3><<<2, 256>>>(g3, be3);
    k_c3<<<65536, 256>>>();                            // y3 hi/lo
    k_mma<2><<<dim3(2, 1024), 256, MMA_SMEM>>>();      // y4 + stats4
    k_params<4><<<2, 256>>>(g4, be4);
    k_final<<<BB*NSAMP, 256>>>(out + BB*NSAMP*3);
}

// round 7
// speedup vs baseline: 1.8298x; 1.2332x over previous
#include <cuda_runtime.h>
#include <cuda_fp16.h>
#include <cstdint>

#define BB 4
#define NN 4096
#define NSAMP 1024
#define KNB 32
#define MTOT (BB*NSAMP*KNB)   // 131072 positions

// ---------------- scratch (device globals; no allocations allowed) ------------
__device__ float g_w21[256*6];
__device__ int   g_knn[MTOT];
__device__ float g_y1[(size_t)MTOT*256];       // conv1 out, [m][c] fp32
__device__ __half g_y1h[(size_t)MTOT*256];     // relu(aff2(y1)) hi, [m][c]
__device__ __half g_y1l[(size_t)MTOT*256];     // lo
__device__ float g_xm[256*BB*NSAMP];           // [c][bs]
__device__ float g_h3[512*BB*NSAMP];           // [row][bs]
__device__ float g_y3[(size_t)MTOT*512];       // conv3 out, [n][512] fp32
__device__ __half g_y3h[(size_t)MTOT*512];
__device__ __half g_y3l[(size_t)MTOT*512];
__device__ float g_y4[(size_t)MTOT*256];       // conv4 out, [n][256] fp32
__device__ __half g_w3bh[512*256], g_w3bl[512*256];
__device__ __half g_w4h[256*512],  g_w4l[256*512];
__device__ float g_sum2[256], g_sq2[256];
__device__ float g_sum3[512], g_sq3[512];
__device__ float g_sum4[256], g_sq4[256];
__device__ float g_s2[256], g_t2[256];
__device__ float g_s3[512], g_t3[512];
__device__ float g_s4[256], g_t4[256];

// ---------------- helpers -----------------------------------------------------
__device__ __forceinline__ uint32_t smem_to_u32(const void* p) {
    uint32_t a;
    asm("{ .reg .u64 t; cvta.to.shared.u64 t, %1; cvt.u32.u64 %0, t; }" : "=r"(a) : "l"(p));
    return a;
}
__device__ __forceinline__ unsigned long long dup2(float a) {
    unsigned int u = __float_as_uint(a);
    return ((unsigned long long)u << 32) | (unsigned long long)u;
}
__device__ __forceinline__ unsigned long long pk64(float a, float b) {
    unsigned long long r;
    asm("mov.b64 %0, {%1,%2};" : "=l"(r) : "f"(a), "f"(b));
    return r;
}
__device__ __forceinline__ void up64(float& a, float& b, unsigned long long v) {
    asm("mov.b64 {%0,%1}, %2;" : "=f"(a), "=f"(b) : "l"(v));
}
__device__ __forceinline__ unsigned long long fma2(unsigned long long a,
                                                   unsigned long long b,
                                                   unsigned long long c) {
    unsigned long long r;
    asm("fma.rn.f32x2 %0, %1, %2, %3;" : "=l"(r) : "l"(a), "l"(b), "l"(c));
    return r;
}
__device__ __forceinline__ unsigned int fmono(float f) {
    unsigned int u = __float_as_uint(f);
    return (u & 0x80000000u) ? ~u : (u | 0x80000000u);
}
__device__ __forceinline__ uint32_t pk2h(__half a, __half b) {
    return ((uint32_t)__half_as_ushort(b) << 16) | (uint32_t)__half_as_ushort(a);
}

#define CP_ASYNC16(dst, src) \
    asm volatile("cp.async.cg.shared.global [%0], [%1], 16;" :: "r"(dst), "l"(src) : "memory")
#define CP_COMMIT() asm volatile("cp.async.commit_group;" ::: "memory")
#define CP_WAIT0() asm volatile("cp.async.wait_group 0;" ::: "memory")
#define CP_WAIT1() asm volatile("cp.async.wait_group 1;" ::: "memory")

__device__ __forceinline__ void ldsm_x4(uint32_t& r0, uint32_t& r1, uint32_t& r2, uint32_t& r3, uint32_t addr) {
    asm volatile("ldmatrix.sync.aligned.m8n8.x4.shared.b16 {%0,%1,%2,%3}, [%4];"
        : "=r"(r0), "=r"(r1), "=r"(r2), "=r"(r3) : "r"(addr));
}
__device__ __forceinline__ void ldsm_x2(uint32_t& r0, uint32_t& r1, uint32_t addr) {
    asm volatile("ldmatrix.sync.aligned.m8n8.x2.shared.b16 {%0,%1}, [%2];"
        : "=r"(r0), "=r"(r1) : "r"(addr));
}
__device__ __forceinline__ void mma16816(float* d, const uint32_t* a, const uint32_t* b) {
    asm volatile("mma.sync.aligned.m16n8k16.row.col.f32.f16.f16.f32 "
        "{%0,%1,%2,%3}, {%4,%5,%6,%7}, {%8,%9}, {%0,%1,%2,%3};"
        : "+f"(d[0]), "+f"(d[1]), "+f"(d[2]), "+f"(d[3])
        : "r"(a[0]), "r"(a[1]), "r"(a[2]), "r"(a[3]), "r"(b[0]), "r"(b[1]));
}

// ---------------- zero stats --------------------------------------------------
__global__ void k_zero() {
    int t = threadIdx.x;  // 512
    if (t < 256) { g_sum2[t]=0.f; g_sq2[t]=0.f; g_sum4[t]=0.f; g_sq4[t]=0.f; }
    g_sum3[t]=0.f; g_sq3[t]=0.f;
}

// ---------------- w21 = w2 @ w1 -----------------------------------------------
__global__ void k_w21(const float* __restrict__ w1, const float* __restrict__ w2) {
    int o = threadIdx.x;
    float acc[6] = {0.f,0.f,0.f,0.f,0.f,0.f};
    for (int c = 0; c < 256; ++c) {
        float w = w2[o*256 + c];
        #pragma unroll
        for (int i = 0; i < 6; ++i) acc[i] = fmaf(w, w1[c*6+i], acc[i]);
    }
    #pragma unroll
    for (int i = 0; i < 6; ++i) g_w21[o*6+i] = acc[i];
}

// ---------------- weight fp16 hi/lo split -------------------------------------
__global__ void k_wsplit(const float* __restrict__ w3, const float* __restrict__ w4) {
    int i = blockIdx.x*256 + threadIdx.x;   // 0..131071
    int r = i >> 8, c = i & 255;
    float v = w3[r*512 + 256 + c];
    __half h = __float2half(v);
    g_w3bh[i] = h; g_w3bl[i] = __float2half(v - __half2float(h));
    float u = w4[i];
    __half h2 = __float2half(u);
    g_w4h[i] = h2; g_w4l[i] = __float2half(u - __half2float(h2));
}

// ---------------- FPS: redux-based, 2 barriers/iter, f32x2 math ----------------
__global__ void __launch_bounds__(1024, 1) k_fps(const float* __restrict__ p,
                                                 float* __restrict__ outC) {
    int b = blockIdx.x;
    const float* pb = p + b*NN*3;
    int t = threadIdx.x;
    int lane = t & 31, w = t >> 5;

    float px[4], py[4], pz[4], dm[4];
    #pragma unroll
    for (int j = 0; j < 4; ++j) {
        int i = t + j*1024;
        px[j] = pb[i*3]; py[j] = pb[i*3+1]; pz[j] = pb[i*3+2];
        dm[j] = 1e10f;
    }
    // packed pairs (j0,j1) and (j2,j3)
    unsigned long long pX01 = pk64(px[0], px[1]), pX23 = pk64(px[2], px[3]);
    unsigned long long pY01 = pk64(py[0], py[1]), pY23 = pk64(py[2], py[3]);
    unsigned long long pZ01 = pk64(pz[0], pz[1]), pZ23 = pk64(pz[2], pz[3]);
    const unsigned long long NEG1 = dup2(-1.0f);

    __shared__ float s_c[4];
    __shared__ unsigned s_v[32];
    __shared__ unsigned s_i[32];

    if (t == 0) {
        float fx = pb[0], fy = pb[1], fz = pb[2];
        s_c[0] = fx; s_c[1] = fy; s_c[2] = fz;
        float* o = outC + b*NSAMP*3;
        o[0] = fx; o[1] = fy; o[2] = fz;
    }
    __syncthreads();

    for (int it = 0; it < NSAMP; ++it) {
        unsigned long long c2x = dup2(s_c[0]), c2y = dup2(s_c[1]), c2z = dup2(s_c[2]);
        // pair 0 (points j=0,1)
        unsigned long long tx = fma2(c2x, NEG1, pX01);
        unsigned long long ty = fma2(c2y, NEG1, pY01);
        unsigned long long tz = fma2(c2z, NEG1, pZ01);
        unsigned long long d2 = fma2(tx, tx, 0ull);
        d2 = fma2(ty, ty, d2);
        d2 = fma2(tz, tz, d2);
        float d0, d1; up64(d0, d1, d2);
        // pair 1 (points j=2,3)
        tx = fma2(c2x, NEG1, pX23);
        ty = fma2(c2y, NEG1, pY23);
        tz = fma2(c2z, NEG1, pZ23);
        d2 = fma2(tx, tx, 0ull);
        d2 = fma2(ty, ty, d2);
        d2 = fma2(tz, tz, d2);
        float d3, d4; up64(d3, d4, d2);

        dm[0] = fminf(dm[0], d0); dm[1] = fminf(dm[1], d1);
        dm[2] = fminf(dm[2], d3); dm[3] = fminf(dm[3], d4);

        float best = fmaxf(fmaxf(dm[0], dm[1]), fmaxf(dm[2], dm[3]));
        int bi = (dm[0] == best) ? t
               : (dm[1] == best) ? t + 1024
               : (dm[2] == best) ? t + 2048 : t + 3072;

        unsigned mv   = fmono(best);
        unsigned wmax = __reduce_max_sync(0xffffffffu, mv);
        unsigned cand = (mv == wmax) ? (unsigned)bi : 0xffffffffu;
        unsigned widx = __reduce_min_sync(0xffffffffu, cand);
        if (lane == 0) { s_v[w] = wmax; s_i[w] = widx; }
        __syncthreads();
        if (w == 0) {
            unsigned mv2 = s_v[lane], id2 = s_i[lane];
            unsigned m2  = __reduce_max_sync(0xffffffffu, mv2);
            unsigned c2  = (mv2 == m2) ? id2 : 0xffffffffu;
            unsigned far = __reduce_min_sync(0xffffffffu, c2);
            if (lane == 0 && it + 1 < NSAMP) {
                float fx = pb[far*3], fy = pb[far*3+1], fz = pb[far*3+2];
                s_c[0] = fx; s_c[1] = fy; s_c[2] = fz;
                float* o = outC + (b*NSAMP + it + 1)*3;
                o[0] = fx; o[1] = fy; o[2] = fz;
            }
        }
        __syncthreads();
    }
}

// ---------------- KNN ---------------------------------------------------------
__global__ void k_knn(const float* __restrict__ p, const float* __restrict__ cent) {
    int cid = blockIdx.x;
    int b = cid >> 10;
    const float* pb = p + b*NN*3;
    int t = threadIdx.x;  // 128
    float cx = cent[cid*3], cy = cent[cid*3+1], cz = cent[cid*3+2];
    float cn = cx*cx + cy*cy + cz*cz;
    unsigned long long key[32];
    #pragma unroll
    for (int j = 0; j < 32; ++j) {
        int i = j*128 + t;
        float x = pb[i*3], y = pb[i*3+1], z = pb[i*3+2];
        float pn = x*x + y*y + z*z;
        float dot = fmaf(cx, x, fmaf(cy, y, cz*z));
        float d2  = fmaf(-2.0f, dot, cn + pn);
        key[j] = ((unsigned long long)fmono(d2) << 32) | (unsigned int)i;
    }
    __shared__ unsigned long long s_part[4];
    __shared__ unsigned long long s_prev;
    unsigned long long prev = 0ull;
    int w = t >> 5, lane = t & 31;
    for (int r = 0; r < KNB; ++r) {
        unsigned long long best = ~0ull;
        #pragma unroll
        for (int j = 0; j < 32; ++j) {
            unsigned long long k = key[j];
            if (k > prev && k < best) best = k;
        }
        #pragma unroll
        for (int off = 16; off; off >>= 1) {
            unsigned long long o = __shfl_down_sync(0xffffffffu, best, off);
            if (o < best) best = o;
        }
        if (lane == 0) s_part[w] = best;
        __syncthreads();
        if (t == 0) {
            unsigned long long m = s_part[0];
            #pragma unroll
            for (int i = 1; i < 4; ++i) if (s_part[i] < m) m = s_part[i];
            s_prev = m;
            g_knn[cid*KNB + r] = (int)(m & 0xffffffffull);
        }
        __syncthreads();
        prev = s_prev;
    }
}

// ------- gather + conv(6->256)+bias -> y1 [m][256] + stage-2 stats ------------
__global__ void k_gconv1(const float* __restrict__ p, const float* __restrict__ f,
                         const float* __restrict__ b2) {
    __shared__ float sw[256*6];
    __shared__ float sbb[256];
    __shared__ float sv[64][6];
    int t = threadIdx.x;
    #pragma unroll
    for (int i = 0; i < 6; ++i) sw[t*6+i] = g_w21[t*6+i];
    sbb[t] = b2[t];
    int m0 = blockIdx.x*64;
    if (t < 64) {
        int m = m0 + t;
        int b = m >> 15;
        int idx = g_knn[m];
        const float* pp = p + b*NN*3 + idx*3;
        const float* ff = f + b*3*NN + idx;
        sv[t][0] = pp[0]; sv[t][1] = pp[1]; sv[t][2] = pp[2];
        sv[t][3] = ff[0]; sv[t][4] = ff[NN]; sv[t][5] = ff[2*NN];
    }
    __syncthreads();
    int c = t;
    float w0 = sw[c*6], w1 = sw[c*6+1], w2 = sw[c*6+2];
    float w3 = sw[c*6+3], w4 = sw[c*6+4], w5 = sw[c*6+5];
    float bias = sbb[c];
    float s = 0.f, q = 0.f;
    #pragma unroll 4
    for (int pp = 0; pp < 64; ++pp) {
        float a = bias;
        a = fmaf(w0, sv[pp][0], a); a = fmaf(w1, sv[pp][1], a); a = fmaf(w2, sv[pp][2], a);
        a = fmaf(w3, sv[pp][3], a); a = fmaf(w4, sv[pp][4], a); a = fmaf(w5, sv[pp][5], a);
        g_y1[(size_t)(m0+pp)*256 + c] = a;
        s += a; q = fmaf(a, a, q);
    }
    atomicAdd(&g_sum2[c], s);
    atomicAdd(&g_sq2[c], q);
}

// ---------------- BN params ---------------------------------------------------
template<int STAGE>
__global__ void k_params(const float* __restrict__ g, const float* __restrict__ be) {
    constexpr int C = (STAGE == 3) ? 512 : 256;
    const float* su = (STAGE == 2) ? g_sum2 : (STAGE == 3) ? g_sum3 : g_sum4;
    const float* sq = (STAGE == 2) ? g_sq2  : (STAGE == 3) ? g_sq3  : g_sq4;
    float* sc = (STAGE == 2) ? g_s2 : (STAGE == 3) ? g_s3 : g_s4;
    float* sh = (STAGE == 2) ? g_t2 : (STAGE == 3) ? g_t3 : g_t4;
    int c = blockIdx.x*blockDim.x + threadIdx.x;
    if (c < C) {
        const float inv = 1.0f / (float)MTOT;
        float mean = su[c]*inv;
        float var  = fmaf(-mean, mean, sq[c]*inv);
        float r    = rsqrtf(var + 1e-5f);
        float s    = g[c]*r;
        sc[c] = s;
        sh[c] = fmaf(-mean, s, be[c]);
    }
}

// ---- c1: relu(aff2(y1)) -> fp16 hi/lo [m][256] + xm [c][bs] ------------------
__global__ void k_c1() {
    int bs = blockIdx.x;      // 4096
    int c  = threadIdx.x;     // 256
    float sc = g_s2[c], hh = g_t2[c];
    size_t base = (size_t)bs*32*256 + c;
    float mx = 0.f;
    #pragma unroll 8
    for (int pp = 0; pp < 32; ++pp) {
        float v = g_y1[base + (size_t)pp*256];
        float a = fmaxf(fmaf(v, sc, hh), 0.f);
        mx = fmaxf(mx, a);
        __half h = __float2half(a);
        g_y1h[base + (size_t)pp*256] = h;
        g_y1l[base + (size_t)pp*256] = __float2half(a - __half2float(h));
    }
    g_xm[c*(BB*NSAMP) + bs] = mx;
}

// ---- c3: relu(aff3(y3)) -> fp16 hi/lo [n][512] -------------------------------
__global__ void k_c3() {
    size_t i = (size_t)blockIdx.x*256 + threadIdx.x;   // float4 index (16.7M)
    float4 v = ((const float4*)g_y3)[i];
    int k = ((int)(i & 127)) * 4;
    float a0 = fmaxf(fmaf(v.x, g_s3[k],   g_t3[k]),   0.f);
    float a1 = fmaxf(fmaf(v.y, g_s3[k+1], g_t3[k+1]), 0.f);
    float a2 = fmaxf(fmaf(v.z, g_s3[k+2], g_t3[k+2]), 0.f);
    float a3 = fmaxf(fmaf(v.w, g_s3[k+3], g_t3[k+3]), 0.f);
    __half h0 = __float2half(a0), h1 = __float2half(a1);
    __half h2 = __float2half(a2), h3 = __float2half(a3);
    __half l0 = __float2half(a0 - __half2float(h0));
    __half l1 = __float2half(a1 - __half2float(h1));
    __half l2 = __float2half(a2 - __half2float(h2));
    __half l3 = __float2half(a3 - __half2float(h3));
    ((uint2*)g_y3h)[i] = make_uint2(pk2h(h0,h1), pk2h(h2,h3));
    ((uint2*)g_y3l)[i] = make_uint2(pk2h(l0,l1), pk2h(l2,l3));
}

// ---------------- small fp32 GEMM: h3 = w3[:, :256] @ xm ----------------------
__global__ void __launch_bounds__(256, 2) k_gemm0(const float* __restrict__ A) {
    constexpr int Nn = BB*NSAMP;     // 4096
    constexpr int Kd = 256, lda = 512;
    __shared__ unsigned long long As[16][128];
    __shared__ float Bs[16][128];
    int m0 = blockIdx.x * 128;
    int n0 = blockIdx.y * 128;
    int t  = threadIdx.x;
    int ar  = t & 127, akq = (t >> 7) * 8;
    int bkr = t >> 4,  bnc = (t & 15) * 8;
    int ty = t >> 4, tx = t & 15;
    unsigned long long acc[8][4];
    #pragma unroll
    for (int i = 0; i < 8; ++i)
        #pragma unroll
        for (int j = 0; j < 4; ++j) acc[i][j] = 0ull;
    for (int k0 = 0; k0 < Kd; k0 += 16) {
        const float* ga = A + (size_t)(m0 + ar)*lda + k0 + akq;
        float4 a0 = *(const float4*)ga;
        float4 a1 = *(const float4*)(ga + 4);
        const float* gb = g_xm + (size_t)(k0 + bkr)*Nn + n0 + bnc;
        float4 b0 = *(const float4*)gb;
        float4 b1 = *(const float4*)(gb + 4);
        __syncthreads();
        As[akq+0][ar] = dup2(a0.x); As[akq+1][ar] = dup2(a0.y);
        As[akq+2][ar] = dup2(a0.z); As[akq+3][ar] = dup2(a0.w);
        As[akq+4][ar] = dup2(a1.x); As[akq+5][ar] = dup2(a1.y);
        As[akq+6][ar] = dup2(a1.z); As[akq+7][ar] = dup2(a1.w);
        *(float4*)&Bs[bkr][bnc]     = b0;
        *(float4*)&Bs[bkr][bnc + 4] = b1;
        __syncthreads();
        #pragma unroll
        for (int kk = 0; kk < 16; ++kk) {
            unsigned long long af[8], bf[4];
            const unsigned long long* ap = &As[kk][ty*8];
            #pragma unroll
            for (int i = 0; i < 8; ++i) af[i] = ap[i];
            const unsigned long long* bp = (const unsigned long long*)&Bs[kk][tx*8];
            #pragma unroll
            for (int j = 0; j < 4; ++j) bf[j] = bp[j];
            #pragma unroll
            for (int i = 0; i < 8; ++i)
                #pragma unroll
                for (int j = 0; j < 4; ++j)
                    asm("fma.rn.f32x2 %0, %1, %2, %0;"
                        : "+l"(acc[i][j]) : "l"(af[i]), "l"(bf[j]));
        }
    }
    #pragma unroll
    for (int i = 0; i < 8; ++i) {
        int gr = m0 + ty*8 + i;
        float out[8];
        #pragma unroll
        for (int j = 0; j < 4; ++j) {
            out[2*j]   = __uint_as_float((unsigned int)(acc[i][j] & 0xffffffffull));
            out[2*j+1] = __uint_as_float((unsigned int)(acc[i][j] >> 32));
        }
        float4* cp = (float4*)(g_h3 + (size_t)gr*Nn + n0 + tx*8);
        cp[0] = make_float4(out[0], out[1], out[2], out[3]);
        cp[1] = make_float4(out[4], out[5], out[6], out[7]);
    }
}

// ---------------- mma.sync fp16 hi/lo GEMM ------------------------------------
// MODE 1: y3[n][512] = w3b(512x256) @ x1^T  + h3-broadcast, stats3
// MODE 2: y4[n][256] = w4 (256x512) @ x3^T,                 stats4
// CTA 128x128, 8 warps (2x4), warp tile 64x32, K-chunk 32, 3-stage cp.async.
// Smem row stride 80B (8-row ldmatrix stride hits 8 distinct 16B banks).
#define STG_BYTES 40960                 // Ah(10240)+Al+Bh+Bl per stage
#define MMA_SMEM  (3*STG_BYTES)

template<int MODE>
__device__ __forceinline__ void mma_issue(uint32_t sbase, int st, int k0,
                                          int m0c, int n0c, int tid) {
    constexpr int Kd = (MODE == 1) ? 256 : 512;
    const __half* __restrict__ Ah = (MODE == 1) ? g_w3bh : g_w4h;
    const __half* __restrict__ Al = (MODE == 1) ? g_w3bl : g_w4l;
    const __half* __restrict__ Bh = (MODE == 1) ? g_y1h : g_y3h;
    const __half* __restrict__ Bl = (MODE == 1) ? g_y1l : g_y3l;
    uint32_t base = sbase + st*STG_BYTES;
    #pragma unroll
    for (int i = 0; i < 4; ++i) {
        int u = tid + i*256;              // 0..1023
        int hl = u >> 9;
        int r = (u >> 2) & 127;
        int q = u & 3;
        const __half* src = (hl ? Al : Ah) + (size_t)(m0c + r)*Kd + k0 + q*8;
        CP_ASYNC16(base + hl*10240 + r*80 + q*16, src);
    }
    #pragma unroll
    for (int i = 0; i < 4; ++i) {
        int u = tid + i*256;
        int hl = u >> 9;
        int r = (u >> 2) & 127;
        int q = u & 3;
        const __half* src = (hl ? Bl : Bh) + (size_t)(n0c + r)*Kd + k0 + q*8;
        CP_ASYNC16(base + 20480 + hl*10240 + r*80 + q*16, src);
    }
}

template<int MODE>
__global__ void __launch_bounds__(256) k_mma() {
    constexpr int Kd = (MODE == 1) ? 256 : 512;
    constexpr int KT = Kd / 32;
    constexpr int Ms = (MODE == 1) ? 512 : 256;    // C row stride
    float* __restrict__ C  = (MODE == 1) ? g_y3 : g_y4;
    float* __restrict__ Su = (MODE == 1) ? g_sum3 : g_sum4;
    float* __restrict__ Sq = (MODE == 1) ? g_sq3 : g_sq4;

    extern __shared__ char smem[];
    uint32_t sb = smem_to_u32(smem);
    int tid = threadIdx.x, lane = tid & 31, wid = tid >> 5;
    int wm = wid >> 2, wn = wid & 3;
    int m0c = blockIdx.x * 128, n0c = blockIdx.y * 128;

    float acc[4][4][4];
    #pragma unroll
    for (int a = 0; a < 4; ++a)
        #pragma unroll
        for (int b = 0; b < 4; ++b)
            #pragma unroll
            for (int c = 0; c < 4; ++c) acc[a][b][c] = 0.f;

    // ldmatrix per-thread address components
    int sel = lane >> 3;
    uint32_t aRow = (uint32_t)((sel & 1)*8 + (lane & 7));
    uint32_t aCol = (uint32_t)((sel >> 1) * 16);
    uint32_t bRow = (uint32_t)(wn*32 + (lane & 7));
    uint32_t bCol = (uint32_t)(((lane >> 3) & 1) * 16);

    mma_issue<MODE>(sb, 0, 0,  m0c, n0c, tid); CP_COMMIT();
    mma_issue<MODE>(sb, 1, 32, m0c, n0c, tid); CP_COMMIT();

    for (int kt = 0; kt < KT; ++kt) {
        if (kt == KT-1) { CP_WAIT0(); } else { CP_WAIT1(); }
        __syncthreads();
        if (kt + 2 < KT) {
            mma_issue<MODE>(sb, (kt+2)%3, (kt+2)*32, m0c, n0c, tid);
            CP_COMMIT();
        }
        uint32_t sA = sb + (kt%3)*STG_BYTES;
        uint32_t sB = sA + 20480;
        #pragma unroll
        for (int ks = 0; ks < 2; ++ks) {
            uint32_t kOff = (uint32_t)(ks*32);
            uint32_t af[4][4], bf[4][2];
            // pass 1: Ah x Bh
            #pragma unroll
            for (int mt = 0; mt < 4; ++mt)
                ldsm_x4(af[mt][0], af[mt][1], af[mt][2], af[mt][3],
                        sA + (uint32_t)(wm*64 + mt*16 + aRow)*80 + kOff + aCol);
            #pragma unroll
            for (int nt = 0; nt < 4; ++nt)
                ldsm_x2(bf[nt][0], bf[nt][1],
                        sB + (bRow + (uint32_t)(nt*8))*80 + kOff + bCol);
            #pragma unroll
            for (int mt = 0; mt < 4; ++mt)
                #pragma unroll
                for (int nt = 0; nt < 4; ++nt)
                    mma16816(acc[mt][nt], af[mt], bf[nt]);
            // pass 2: Ah x Bl
            #pragma unroll
            for (int nt = 0; nt < 4; ++nt)
                ldsm_x2(bf[nt][0], bf[nt][1],
                        sB + 10240 + (bRow + (uint32_t)(nt*8))*80 + kOff + bCol);
            #pragma unroll
            for (int mt = 0; mt < 4; ++mt)
                #pragma unroll
                for (int nt = 0; nt < 4; ++nt)
                    mma16816(acc[mt][nt], af[mt], bf[nt]);
            // pass 3: Al x Bh
            #pragma unroll
            for (int mt = 0; mt < 4; ++mt)
                ldsm_x4(af[mt][0], af[mt][1], af[mt][2], af[mt][3],
                        sA + 10240 + (uint32_t)(wm*64 + mt*16 + aRow)*80 + kOff + aCol);
            #pragma unroll
            for (int nt = 0; nt < 4; ++nt)
                ldsm_x2(bf[nt][0], bf[nt][1],
                        sB + (bRow + (uint32_t)(nt*8))*80 + kOff + bCol);
            #pragma unroll
            for (int mt = 0; mt < 4; ++mt)
                #pragma unroll
                for (int nt = 0; nt < 4; ++nt)
                    mma16816(acc[mt][nt], af[mt], bf[nt]);
        }
    }

    // ---------------- epilogue: store C (+h3), fused BN stats ----------------
    __syncthreads();                       // smem reuse for reduction
    float* redS = (float*)smem;            // [128][16]
    float* redQ = (float*)(smem + 8192);
    int qrow = lane >> 2, qcol = lane & 3;

    #pragma unroll
    for (int mt = 0; mt < 4; ++mt) {
        #pragma unroll
        for (int hf = 0; hf < 2; ++hf) {
            int mloc = wm*64 + mt*16 + hf*8 + qrow;
            int mg = m0c + mloc;
            float h3v = 0.f;
            if (MODE == 1) h3v = g_h3[(size_t)mg*(BB*NSAMP) + (n0c >> 5) + wn];
            float s = 0.f, q = 0.f;
            #pragma unroll
            for (int nt = 0; nt < 4; ++nt) {
                #pragma unroll
                for (int j = 0; j < 2; ++j) {
                    float v = acc[mt][nt][hf*2 + j] + h3v;
                    int ng = n0c + wn*32 + nt*8 + qcol*2 + j;
                    C[(size_t)ng*Ms + mg] = v;
                    s += v; q = fmaf(v, v, q);
                }
            }
            redS[mloc*16 + wn*4 + qcol] = s;
            redQ[mloc*16 + wn*4 + qcol] = q;
        }
    }
    __syncthreads();
    if (tid < 128) {
        float s = 0.f;
        #pragma unroll
        for (int i = 0; i < 16; ++i) s += redS[tid*16 + i];
        atomicAdd(&Su[m0c + tid], s);
    } else {
        int m = tid - 128;
        float q = 0.f;
        #pragma unroll
        for (int i = 0; i < 16; ++i) q += redQ[m*16 + i];
        atomicAdd(&Sq[m0c + m], q);
    }
}

// ---------------- final: out_feat = max_k relu(aff4(y4)) ----------------------
__global__ void k_final(float* __restrict__ out) {
    int bs = blockIdx.x;   // 4096
    int c  = threadIdx.x;  // 256
    float sc = g_s4[c], hh = g_t4[c];
    size_t base = (size_t)bs*32*256 + c;
    float mx = 0.f;
    #pragma unroll 8
    for (int pp = 0; pp < 32; ++pp) {
        float v = g_y4[base + (size_t)pp*256];
        mx = fmaxf(mx, fmaxf(fmaf(v, sc, hh), 0.f));
    }
    int b = bs >> 10, sI = bs & 1023;
    out[(((b << 8) + c) << 10) + sI] = mx;
}

// ---------------- launcher ----------------------------------------------------
extern "C" void kernel_launch(void* const* d_in, const int* in_sizes, int n_in,
                              void* d_out, int out_size) {
    const float* p   = (const float*)d_in[0];
    const float* f   = (const float*)d_in[1];
    const float* w1  = (const float*)d_in[2];
    const float* w2  = (const float*)d_in[3];
    const float* b2  = (const float*)d_in[4];
    const float* g2  = (const float*)d_in[5];
    const float* be2 = (const float*)d_in[6];
    const float* w3  = (const float*)d_in[7];
    const float* g3  = (const float*)d_in[8];
    const float* be3 = (const float*)d_in[9];
    const float* w4  = (const float*)d_in[10];
    const float* g4  = (const float*)d_in[11];
    const float* be4 = (const float*)d_in[12];
    float* out = (float*)d_out;

    cudaFuncSetAttribute(k_mma<1>, cudaFuncAttributeMaxDynamicSharedMemorySize, MMA_SMEM);
    cudaFuncSetAttribute(k_mma<2>, cudaFuncAttributeMaxDynamicSharedMemorySize, MMA_SMEM);

    k_zero<<<1, 512>>>();
    k_w21<<<1, 256>>>(w1, w2);
    k_wsplit<<<512, 256>>>(w3, w4);
    k_fps<<<BB, 1024>>>(p, out);                       // cntrd -> d_out[0..12288)
    k_knn<<<BB*NSAMP, 128>>>(p, out);
    k_gconv1<<<MTOT/64, 256>>>(p, f, b2);              // y1 + stats2
    k_params<2><<<2, 256>>>(g2, be2);
    k_c1<<<BB*NSAMP, 256>>>();                         // y1 hi/lo + xm
    k_gemm0<<<dim3(4, 32), 256>>>(w3);                 // h3 = w3a @ xm
    k_mma<1><<<dim3(4, 1024), 256, MMA_SMEM>>>();      // y3 + stats3
    k_params<3><<<2, 256>>>(g3, be3);
    k_c3<<<65536, 256>>>();                            // y3 hi/lo
    k_mma<2><<<dim3(2, 1024), 256, MMA_SMEM>>>();      // y4 + stats4
    k_params<4><<<2, 256>>>(g4, be4);
    k_final<<<BB*NSAMP, 256>>>(out + BB*NSAMP*3);
}

// round 8
// speedup vs baseline: 1.9548x; 1.0683x over previous
#include <cuda_runtime.h>
#include <cuda_fp16.h>
#include <cstdint>

#define BB 4
#define NN 4096
#define NSAMP 1024
#define KNB 32
#define MTOT (BB*NSAMP*KNB)   // 131072 positions

// ---------------- scratch (device globals; no allocations allowed) ------------
__device__ float g_w21[256*6];
__device__ int   g_knn[MTOT];
__device__ float g_y1[(size_t)MTOT*256];       // conv1 out, [m][c] fp32
__device__ __half g_y1h[(size_t)MTOT*256];     // relu(aff2(y1)) hi, [m][c]
__device__ __half g_y1l[(size_t)MTOT*256];     // lo
__device__ float g_xm[256*BB*NSAMP];           // [c][bs]
__device__ float g_h3[512*BB*NSAMP];           // [row][bs]
__device__ float g_y3[(size_t)MTOT*512];       // conv3 out, [n][512] fp32
__device__ __half g_y3h[(size_t)MTOT*512];
__device__ __half g_y3l[(size_t)MTOT*512];
__device__ float g_y4[(size_t)MTOT*256];       // conv4 out, [n][256] fp32
__device__ __half g_w3bh[512*256], g_w3bl[512*256];
__device__ __half g_w4h[256*512],  g_w4l[256*512];
__device__ float g_sum2[256], g_sq2[256];
__device__ float g_sum3[512], g_sq3[512];
__device__ float g_sum4[256], g_sq4[256];
__device__ float g_s2[256], g_t2[256];
__device__ float g_s3[512], g_t3[512];
__device__ float g_s4[256], g_t4[256];

// ---------------- helpers -----------------------------------------------------
__device__ __forceinline__ uint32_t smem_to_u32(const void* p) {
    uint32_t a;
    asm("{ .reg .u64 t; cvta.to.shared.u64 t, %1; cvt.u32.u64 %0, t; }" : "=r"(a) : "l"(p));
    return a;
}
__device__ __forceinline__ unsigned long long dup2(float a) {
    unsigned int u = __float_as_uint(a);
    return ((unsigned long long)u << 32) | (unsigned long long)u;
}
__device__ __forceinline__ unsigned long long pk64(float a, float b) {
    unsigned long long r;
    asm("mov.b64 %0, {%1,%2};" : "=l"(r) : "f"(a), "f"(b));
    return r;
}
__device__ __forceinline__ void up64(float& a, float& b, unsigned long long v) {
    asm("mov.b64 {%0,%1}, %2;" : "=f"(a), "=f"(b) : "l"(v));
}
__device__ __forceinline__ unsigned long long fma2(unsigned long long a,
                                                   unsigned long long b,
                                                   unsigned long long c) {
    unsigned long long r;
    asm("fma.rn.f32x2 %0, %1, %2, %3;" : "=l"(r) : "l"(a), "l"(b), "l"(c));
    return r;
}
__device__ __forceinline__ unsigned int fmono(float f) {
    unsigned int u = __float_as_uint(f);
    return (u & 0x80000000u) ? ~u : (u | 0x80000000u);
}
__device__ __forceinline__ uint32_t pk2h(__half a, __half b) {
    return ((uint32_t)__half_as_ushort(b) << 16) | (uint32_t)__half_as_ushort(a);
}

#define CP_ASYNC16(dst, src) \
    asm volatile("cp.async.cg.shared.global [%0], [%1], 16;" :: "r"(dst), "l"(src) : "memory")
#define CP_COMMIT() asm volatile("cp.async.commit_group;" ::: "memory")
#define CP_WAIT0() asm volatile("cp.async.wait_group 0;" ::: "memory")
#define CP_WAIT1() asm volatile("cp.async.wait_group 1;" ::: "memory")
#define BAR_ARRIVE(id, cnt) asm volatile("bar.arrive %0, %1;" :: "r"(id), "r"(cnt) : "memory")
#define BAR_SYNC2(id, cnt)  asm volatile("bar.sync %0, %1;"   :: "r"(id), "r"(cnt) : "memory")

__device__ __forceinline__ void ldsm_x4(uint32_t& r0, uint32_t& r1, uint32_t& r2, uint32_t& r3, uint32_t addr) {
    asm volatile("ldmatrix.sync.aligned.m8n8.x4.shared.b16 {%0,%1,%2,%3}, [%4];"
        : "=r"(r0), "=r"(r1), "=r"(r2), "=r"(r3) : "r"(addr));
}
__device__ __forceinline__ void ldsm_x2(uint32_t& r0, uint32_t& r1, uint32_t addr) {
    asm volatile("ldmatrix.sync.aligned.m8n8.x2.shared.b16 {%0,%1}, [%2];"
        : "=r"(r0), "=r"(r1) : "r"(addr));
}
__device__ __forceinline__ void mma16816(float* d, const uint32_t* a, const uint32_t* b) {
    asm volatile("mma.sync.aligned.m16n8k16.row.col.f32.f16.f16.f32 "
        "{%0,%1,%2,%3}, {%4,%5,%6,%7}, {%8,%9}, {%0,%1,%2,%3};"
        : "+f"(d[0]), "+f"(d[1]), "+f"(d[2]), "+f"(d[3])
        : "r"(a[0]), "r"(a[1]), "r"(a[2]), "r"(a[3]), "r"(b[0]), "r"(b[1]));
}

// ---------------- zero stats --------------------------------------------------
__global__ void k_zero() {
    int t = threadIdx.x;  // 512
    if (t < 256) { g_sum2[t]=0.f; g_sq2[t]=0.f; g_sum4[t]=0.f; g_sq4[t]=0.f; }
    g_sum3[t]=0.f; g_sq3[t]=0.f;
}

// ---------------- w21 = w2 @ w1 -----------------------------------------------
__global__ void k_w21(const float* __restrict__ w1, const float* __restrict__ w2) {
    int o = threadIdx.x;
    float acc[6] = {0.f,0.f,0.f,0.f,0.f,0.f};
    for (int c = 0; c < 256; ++c) {
        float w = w2[o*256 + c];
        #pragma unroll
        for (int i = 0; i < 6; ++i) acc[i] = fmaf(w, w1[c*6+i], acc[i]);
    }
    #pragma unroll
    for (int i = 0; i < 6; ++i) g_w21[o*6+i] = acc[i];
}

// ---------------- weight fp16 hi/lo split -------------------------------------
__global__ void k_wsplit(const float* __restrict__ w3, const float* __restrict__ w4) {
    int i = blockIdx.x*256 + threadIdx.x;   // 0..131071
    int r = i >> 8, c = i & 255;
    float v = w3[r*512 + 256 + c];
    __half h = __float2half(v);
    g_w3bh[i] = h; g_w3bl[i] = __float2half(v - __half2float(h));
    float u = w4[i];
    __half h2 = __float2half(u);
    g_w4h[i] = h2; g_w4l[i] = __float2half(u - __half2float(h2));
}

// ---------------- FPS: redux + arrive/sync split barrier ----------------------
__global__ void __launch_bounds__(1024, 1) k_fps(const float* __restrict__ p,
                                                 float* __restrict__ outC) {
    int b = blockIdx.x;
    const float* pb = p + b*NN*3;
    int t = threadIdx.x;
    int lane = t & 31, w = t >> 5;

    float px[4], py[4], pz[4], dm[4];
    #pragma unroll
    for (int j = 0; j < 4; ++j) {
        int i = t + j*1024;
        px[j] = pb[i*3]; py[j] = pb[i*3+1]; pz[j] = pb[i*3+2];
        dm[j] = 1e10f;
    }
    unsigned long long pX01 = pk64(px[0], px[1]), pX23 = pk64(px[2], px[3]);
    unsigned long long pY01 = pk64(py[0], py[1]), pY23 = pk64(py[2], py[3]);
    unsigned long long pZ01 = pk64(pz[0], pz[1]), pZ23 = pk64(pz[2], pz[3]);
    const unsigned long long NEG1 = dup2(-1.0f);

    __shared__ float s_c[4];
    __shared__ unsigned s_v[32];
    __shared__ unsigned s_i[32];

    if (t == 0) {
        float fx = pb[0], fy = pb[1], fz = pb[2];
        s_c[0] = fx; s_c[1] = fy; s_c[2] = fz;
        float* o = outC + b*NSAMP*3;
        o[0] = fx; o[1] = fy; o[2] = fz;
    }
    __syncthreads();

    for (int it = 0; it < NSAMP; ++it) {
        unsigned long long c2x = dup2(s_c[0]), c2y = dup2(s_c[1]), c2z = dup2(s_c[2]);
        unsigned long long tx = fma2(c2x, NEG1, pX01);
        unsigned long long ty = fma2(c2y, NEG1, pY01);
        unsigned long long tz = fma2(c2z, NEG1, pZ01);
        unsigned long long d2 = fma2(tx, tx, 0ull);
        d2 = fma2(ty, ty, d2);
        d2 = fma2(tz, tz, d2);
        float d0, d1; up64(d0, d1, d2);
        tx = fma2(c2x, NEG1, pX23);
        ty = fma2(c2y, NEG1, pY23);
        tz = fma2(c2z, NEG1, pZ23);
        d2 = fma2(tx, tx, 0ull);
        d2 = fma2(ty, ty, d2);
        d2 = fma2(tz, tz, d2);
        float d3, d4; up64(d3, d4, d2);

        dm[0] = fminf(dm[0], d0); dm[1] = fminf(dm[1], d1);
        dm[2] = fminf(dm[2], d3); dm[3] = fminf(dm[3], d4);

        float best = fmaxf(fmaxf(dm[0], dm[1]), fmaxf(dm[2], dm[3]));
        int bi = (dm[0] == best) ? t
               : (dm[1] == best) ? t + 1024
               : (dm[2] == best) ? t + 2048 : t + 3072;

        unsigned mv   = fmono(best);
        unsigned wmax = __reduce_max_sync(0xffffffffu, mv);
        unsigned cand = (mv == wmax) ? (unsigned)bi : 0xffffffffu;
        unsigned widx = __reduce_min_sync(0xffffffffu, cand);
        if (lane == 0) { s_v[w] = wmax; s_i[w] = widx; }

        if (w == 0) {
            BAR_SYNC2(1, 1024);           // wait for all 31 arrivals + own
            unsigned mv2 = s_v[lane], id2 = s_i[lane];
            unsigned m2  = __reduce_max_sync(0xffffffffu, mv2);
            unsigned c2  = (mv2 == m2) ? id2 : 0xffffffffu;
            unsigned far = __reduce_min_sync(0xffffffffu, c2);
            if (lane == 0 && it + 1 < NSAMP) {
                float fx = pb[far*3], fy = pb[far*3+1], fz = pb[far*3+2];
                s_c[0] = fx; s_c[1] = fy; s_c[2] = fz;
                float* o = outC + (b*NSAMP + it + 1)*3;
                o[0] = fx; o[1] = fy; o[2] = fz;
            }
        } else {
            BAR_ARRIVE(1, 1024);          // non-blocking post
        }
        __syncthreads();
    }
}

// ---------------- KNN ---------------------------------------------------------
__global__ void k_knn(const float* __restrict__ p, const float* __restrict__ cent) {
    int cid = blockIdx.x;
    int b = cid >> 10;
    const float* pb = p + b*NN*3;
    int t = threadIdx.x;  // 128
    float cx = cent[cid*3], cy = cent[cid*3+1], cz = cent[cid*3+2];
    float cn = cx*cx + cy*cy + cz*cz;
    unsigned long long key[32];
    #pragma unroll
    for (int j = 0; j < 32; ++j) {
        int i = j*128 + t;
        float x = pb[i*3], y = pb[i*3+1], z = pb[i*3+2];
        float pn = x*x + y*y + z*z;
        float dot = fmaf(cx, x, fmaf(cy, y, cz*z));
        float d2  = fmaf(-2.0f, dot, cn + pn);
        key[j] = ((unsigned long long)fmono(d2) << 32) | (unsigned int)i;
    }
    __shared__ unsigned long long s_part[4];
    __shared__ unsigned long long s_prev;
    unsigned long long prev = 0ull;
    int w = t >> 5, lane = t & 31;
    for (int r = 0; r < KNB; ++r) {
        unsigned long long best = ~0ull;
        #pragma unroll
        for (int j = 0; j < 32; ++j) {
            unsigned long long k = key[j];
            if (k > prev && k < best) best = k;
        }
        #pragma unroll
        for (int off = 16; off; off >>= 1) {
            unsigned long long o = __shfl_down_sync(0xffffffffu, best, off);
            if (o < best) best = o;
        }
        if (lane == 0) s_part[w] = best;
        __syncthreads();
        if (t == 0) {
            unsigned long long m = s_part[0];
            #pragma unroll
            for (int i = 1; i < 4; ++i) if (s_part[i] < m) m = s_part[i];
            s_prev = m;
            g_knn[cid*KNB + r] = (int)(m & 0xffffffffull);
        }
        __syncthreads();
        prev = s_prev;
    }
}

// ------- gather + conv(6->256)+bias -> y1 [m][256] + stage-2 stats ------------
__global__ void k_gconv1(const float* __restrict__ p, const float* __restrict__ f,
                         const float* __restrict__ b2) {
    __shared__ float sw[256*6];
    __shared__ float sbb[256];
    __shared__ float sv[64][6];
    int t = threadIdx.x;
    #pragma unroll
    for (int i = 0; i < 6; ++i) sw[t*6+i] = g_w21[t*6+i];
    sbb[t] = b2[t];
    int m0 = blockIdx.x*64;
    if (t < 64) {
        int m = m0 + t;
        int b = m >> 15;
        int idx = g_knn[m];
        const float* pp = p + b*NN*3 + idx*3;
        const float* ff = f + b*3*NN + idx;
        sv[t][0] = pp[0]; sv[t][1] = pp[1]; sv[t][2] = pp[2];
        sv[t][3] = ff[0]; sv[t][4] = ff[NN]; sv[t][5] = ff[2*NN];
    }
    __syncthreads();
    int c = t;
    float w0 = sw[c*6], w1 = sw[c*6+1], w2 = sw[c*6+2];
    float w3 = sw[c*6+3], w4 = sw[c*6+4], w5 = sw[c*6+5];
    float bias = sbb[c];
    float s = 0.f, q = 0.f;
    #pragma unroll 4
    for (int pp = 0; pp < 64; ++pp) {
        float a = bias;
        a = fmaf(w0, sv[pp][0], a); a = fmaf(w1, sv[pp][1], a); a = fmaf(w2, sv[pp][2], a);
        a = fmaf(w3, sv[pp][3], a); a = fmaf(w4, sv[pp][4], a); a = fmaf(w5, sv[pp][5], a);
        g_y1[(size_t)(m0+pp)*256 + c] = a;
        s += a; q = fmaf(a, a, q);
    }
    atomicAdd(&g_sum2[c], s);
    atomicAdd(&g_sq2[c], q);
}

// ---------------- BN params ---------------------------------------------------
template<int STAGE>
__global__ void k_params(const float* __restrict__ g, const float* __restrict__ be) {
    constexpr int C = (STAGE == 3) ? 512 : 256;
    const float* su = (STAGE == 2) ? g_sum2 : (STAGE == 3) ? g_sum3 : g_sum4;
    const float* sq = (STAGE == 2) ? g_sq2  : (STAGE == 3) ? g_sq3  : g_sq4;
    float* sc = (STAGE == 2) ? g_s2 : (STAGE == 3) ? g_s3 : g_s4;
    float* sh = (STAGE == 2) ? g_t2 : (STAGE == 3) ? g_t3 : g_t4;
    int c = blockIdx.x*blockDim.x + threadIdx.x;
    if (c < C) {
        const float inv = 1.0f / (float)MTOT;
        float mean = su[c]*inv;
        float var  = fmaf(-mean, mean, sq[c]*inv);
        float r    = rsqrtf(var + 1e-5f);
        float s    = g[c]*r;
        sc[c] = s;
        sh[c] = fmaf(-mean, s, be[c]);
    }
}

// ---- c1: relu(aff2(y1)) -> fp16 hi/lo [m][256] + xm [c][bs] ------------------
__global__ void k_c1() {
    int bs = blockIdx.x;      // 4096
    int c  = threadIdx.x;     // 256
    float sc = g_s2[c], hh = g_t2[c];
    size_t base = (size_t)bs*32*256 + c;
    float mx = 0.f;
    #pragma unroll 8
    for (int pp = 0; pp < 32; ++pp) {
        float v = g_y1[base + (size_t)pp*256];
        float a = fmaxf(fmaf(v, sc, hh), 0.f);
        mx = fmaxf(mx, a);
        __half h = __float2half(a);
        g_y1h[base + (size_t)pp*256] = h;
        g_y1l[base + (size_t)pp*256] = __float2half(a - __half2float(h));
    }
    g_xm[c*(BB*NSAMP) + bs] = mx;
}

// ---- c3: relu(aff3(y3)) -> fp16 hi/lo [n][512] -------------------------------
__global__ void k_c3() {
    size_t i = (size_t)blockIdx.x*256 + threadIdx.x;   // float4 index (16.7M)
    float4 v = ((const float4*)g_y3)[i];
    int k = ((int)(i & 127)) * 4;
    float a0 = fmaxf(fmaf(v.x, g_s3[k],   g_t3[k]),   0.f);
    float a1 = fmaxf(fmaf(v.y, g_s3[k+1], g_t3[k+1]), 0.f);
    float a2 = fmaxf(fmaf(v.z, g_s3[k+2], g_t3[k+2]), 0.f);
    float a3 = fmaxf(fmaf(v.w, g_s3[k+3], g_t3[k+3]), 0.f);
    __half h0 = __float2half(a0), h1 = __float2half(a1);
    __half h2 = __float2half(a2), h3 = __float2half(a3);
    __half l0 = __float2half(a0 - __half2float(h0));
    __half l1 = __float2half(a1 - __half2float(h1));
    __half l2 = __float2half(a2 - __half2float(h2));
    __half l3 = __float2half(a3 - __half2float(h3));
    ((uint2*)g_y3h)[i] = make_uint2(pk2h(h0,h1), pk2h(h2,h3));
    ((uint2*)g_y3l)[i] = make_uint2(pk2h(l0,l1), pk2h(l2,l3));
}

// ---------------- small fp32 GEMM: h3 = w3[:, :256] @ xm ----------------------
__global__ void __launch_bounds__(256, 2) k_gemm0(const float* __restrict__ A) {
    constexpr int Nn = BB*NSAMP;     // 4096
    constexpr int Kd = 256, lda = 512;
    __shared__ unsigned long long As[16][128];
    __shared__ float Bs[16][128];
    int m0 = blockIdx.x * 128;
    int n0 = blockIdx.y * 128;
    int t  = threadIdx.x;
    int ar  = t & 127, akq = (t >> 7) * 8;
    int bkr = t >> 4,  bnc = (t & 15) * 8;
    int ty = t >> 4, tx = t & 15;
    unsigned long long acc[8][4];
    #pragma unroll
    for (int i = 0; i < 8; ++i)
        #pragma unroll
        for (int j = 0; j < 4; ++j) acc[i][j] = 0ull;
    for (int k0 = 0; k0 < Kd; k0 += 16) {
        const float* ga = A + (size_t)(m0 + ar)*lda + k0 + akq;
        float4 a0 = *(const float4*)ga;
        float4 a1 = *(const float4*)(ga + 4);
        const float* gb = g_xm + (size_t)(k0 + bkr)*Nn + n0 + bnc;
        float4 b0 = *(const float4*)gb;
        float4 b1 = *(const float4*)(gb + 4);
        __syncthreads();
        As[akq+0][ar] = dup2(a0.x); As[akq+1][ar] = dup2(a0.y);
        As[akq+2][ar] = dup2(a0.z); As[akq+3][ar] = dup2(a0.w);
        As[akq+4][ar] = dup2(a1.x); As[akq+5][ar] = dup2(a1.y);
        As[akq+6][ar] = dup2(a1.z); As[akq+7][ar] = dup2(a1.w);
        *(float4*)&Bs[bkr][bnc]     = b0;
        *(float4*)&Bs[bkr][bnc + 4] = b1;
        __syncthreads();
        #pragma unroll
        for (int kk = 0; kk < 16; ++kk) {
            unsigned long long af[8], bf[4];
            const unsigned long long* ap = &As[kk][ty*8];
            #pragma unroll
            for (int i = 0; i < 8; ++i) af[i] = ap[i];
            const unsigned long long* bp = (const unsigned long long*)&Bs[kk][tx*8];
            #pragma unroll
            for (int j = 0; j < 4; ++j) bf[j] = bp[j];
            #pragma unroll
            for (int i = 0; i < 8; ++i)
                #pragma unroll
                for (int j = 0; j < 4; ++j)
                    asm("fma.rn.f32x2 %0, %1, %2, %0;"
                        : "+l"(acc[i][j]) : "l"(af[i]), "l"(bf[j]));
        }
    }
    #pragma unroll
    for (int i = 0; i < 8; ++i) {
        int gr = m0 + ty*8 + i;
        float out[8];
        #pragma unroll
        for (int j = 0; j < 4; ++j) {
            out[2*j]   = __uint_as_float((unsigned int)(acc[i][j] & 0xffffffffull));
            out[2*j+1] = __uint_as_float((unsigned int)(acc[i][j] >> 32));
        }
        float4* cp = (float4*)(g_h3 + (size_t)gr*Nn + n0 + tx*8);
        cp[0] = make_float4(out[0], out[1], out[2], out[3]);
        cp[1] = make_float4(out[4], out[5], out[6], out[7]);
    }
}

// ---------------- mma.sync fp16 hi/lo GEMM, CTA 128x256 -----------------------
// MODE 1: y3[n][512] = w3b(512x256) @ x1^T  + h3-broadcast, stats3
// MODE 2: y4[n][256] = w4 (256x512) @ x3^T,                 stats4
// 8 warps (2x4), warp tile 64x64, K-chunk 32, 3-stage cp.async.
// Stage: Ah[0,10240) Al[10240,20480) Bh[20480,40960) Bl[40960,61440)
#define STG_BYTES 61440
#define MMA_SMEM  (3*STG_BYTES)     // 184320

template<int MODE>
__device__ __forceinline__ void mma_issue(uint32_t sbase, int st, int k0,
                                          int m0c, int n0c, int tid) {
    constexpr int Kd = (MODE == 1) ? 256 : 512;
    const __half* __restrict__ Ah = (MODE == 1) ? g_w3bh : g_w4h;
    const __half* __restrict__ Al = (MODE == 1) ? g_w3bl : g_w4l;
    const __half* __restrict__ Bh = (MODE == 1) ? g_y1h : g_y3h;
    const __half* __restrict__ Bl = (MODE == 1) ? g_y1l : g_y3l;
    uint32_t base = sbase + st*STG_BYTES;
    #pragma unroll
    for (int i = 0; i < 4; ++i) {            // A: 128 rows x 4 x 16B, hi+lo
        int u = tid + i*256;                 // 0..1023
        int hl = u >> 9;
        int r = (u >> 2) & 127;
        int q = u & 3;
        const __half* src = (hl ? Al : Ah) + (size_t)(m0c + r)*Kd + k0 + q*8;
        CP_ASYNC16(base + hl*10240 + r*80 + q*16, src);
    }
    #pragma unroll
    for (int i = 0; i < 8; ++i) {            // B: 256 rows x 4 x 16B, hi+lo
        int u = tid + i*256;                 // 0..2047
        int hl = u >> 10;
        int r = (u >> 2) & 255;
        int q = u & 3;
        const __half* src = (hl ? Bl : Bh) + (size_t)(n0c + r)*Kd + k0 + q*8;
        CP_ASYNC16(base + 20480 + hl*20480 + r*80 + q*16, src);
    }
}

template<int MODE>
__global__ void __launch_bounds__(256) k_mma() {
    constexpr int Kd = (MODE == 1) ? 256 : 512;
    constexpr int KT = Kd / 32;
    constexpr int Ms = (MODE == 1) ? 512 : 256;    // C row stride
    float* __restrict__ C  = (MODE == 1) ? g_y3 : g_y4;
    float* __restrict__ Su = (MODE == 1) ? g_sum3 : g_sum4;
    float* __restrict__ Sq = (MODE == 1) ? g_sq3 : g_sq4;

    extern __shared__ char smem[];
    uint32_t sb = smem_to_u32(smem);
    int tid = threadIdx.x, lane = tid & 31, wid = tid >> 5;
    int wm = wid >> 2, wn = wid & 3;               // 2 x 4 warps
    int m0c = blockIdx.x * 128, n0c = blockIdx.y * 256;

    float acc[4][8][4];
    #pragma unroll
    for (int a = 0; a < 4; ++a)
        #pragma unroll
        for (int b = 0; b < 8; ++b)
            #pragma unroll
            for (int c = 0; c < 4; ++c) acc[a][b][c] = 0.f;

    int sel = lane >> 3;
    uint32_t aRow = (uint32_t)((sel & 1)*8 + (lane & 7));
    uint32_t aCol = (uint32_t)((sel >> 1) * 16);
    uint32_t bRowB = (uint32_t)(wn*64 + (lane & 7));
    uint32_t bCol = (uint32_t)(((lane >> 3) & 1) * 16);

    mma_issue<MODE>(sb, 0, 0,  m0c, n0c, tid); CP_COMMIT();
    mma_issue<MODE>(sb, 1, 32, m0c, n0c, tid); CP_COMMIT();

    for (int kt = 0; kt < KT; ++kt) {
        if (kt == KT-1) { CP_WAIT0(); } else { CP_WAIT1(); }
        __syncthreads();
        if (kt + 2 < KT) {
            mma_issue<MODE>(sb, (kt+2)%3, (kt+2)*32, m0c, n0c, tid);
            CP_COMMIT();
        }
        uint32_t sA = sb + (kt%3)*STG_BYTES;
        #pragma unroll
        for (int ks = 0; ks < 2; ++ks) {
            uint32_t kOff = (uint32_t)(ks*32);
            uint32_t ah[4][4], axl[4][4], bf[8][2];
            // load Ah + Bh
            #pragma unroll
            for (int mt = 0; mt < 4; ++mt)
                ldsm_x4(ah[mt][0], ah[mt][1], ah[mt][2], ah[mt][3],
                        sA + (uint32_t)(wm*64 + mt*16 + aRow)*80 + kOff + aCol);
            #pragma unroll
            for (int nt = 0; nt < 8; ++nt)
                ldsm_x2(bf[nt][0], bf[nt][1],
                        sA + 20480 + (bRowB + (uint32_t)(nt*8))*80 + kOff + bCol);
            // P1: Ah x Bh
            #pragma unroll
            for (int mt = 0; mt < 4; ++mt)
                #pragma unroll
                for (int nt = 0; nt < 8; ++nt)
                    mma16816(acc[mt][nt], ah[mt], bf[nt]);
            // P2: Al x Bh (reuse Bh regs)
            #pragma unroll
            for (int mt = 0; mt < 4; ++mt)
                ldsm_x4(axl[mt][0], axl[mt][1], axl[mt][2], axl[mt][3],
                        sA + 10240 + (uint32_t)(wm*64 + mt*16 + aRow)*80 + kOff + aCol);
            #pragma unroll
            for (int mt = 0; mt < 4; ++mt)
                #pragma unroll
                for (int nt = 0; nt < 8; ++nt)
                    mma16816(acc[mt][nt], axl[mt], bf[nt]);
            // P3: Ah x Bl (reuse Ah regs, overwrite bf with Bl)
            #pragma unroll
            for (int nt = 0; nt < 8; ++nt)
                ldsm_x2(bf[nt][0], bf[nt][1],
                        sA + 40960 + (bRowB + (uint32_t)(nt*8))*80 + kOff + bCol);
            #pragma unroll
            for (int mt = 0; mt < 4; ++mt)
                #pragma unroll
                for (int nt = 0; nt < 8; ++nt)
                    mma16816(acc[mt][nt], ah[mt], bf[nt]);
        }
    }

    // ---------------- epilogue: store C (+h3), fused BN stats ----------------
    __syncthreads();                       // smem reuse for reduction
    float* redS = (float*)smem;            // [128][16]
    float* redQ = (float*)(smem + 8192);
    int qrow = lane >> 2, qcol = lane & 3;

    #pragma unroll
    for (int mt = 0; mt < 4; ++mt) {
        #pragma unroll
        for (int hf = 0; hf < 2; ++hf) {
            int mloc = wm*64 + mt*16 + hf*8 + qrow;
            int mg = m0c + mloc;
            float h3a = 0.f, h3b = 0.f;
            if (MODE == 1) {
                int gidx = (n0c >> 5) + wn*2;
                h3a = g_h3[(size_t)mg*(BB*NSAMP) + gidx];
                h3b = g_h3[(size_t)mg*(BB*NSAMP) + gidx + 1];
            }
            float s = 0.f, q = 0.f;
            #pragma unroll
            for (int nt = 0; nt < 8; ++nt) {
                float h3v = (nt < 4) ? h3a : h3b;
                #pragma unroll
                for (int j = 0; j < 2; ++j) {
                    float v = acc[mt][nt][hf*2 + j] + h3v;
                    int ng = n0c + wn*64 + nt*8 + qcol*2 + j;
                    C[(size_t)ng*Ms + mg] = v;
                    s += v; q = fmaf(v, v, q);
                }
            }
            redS[mloc*16 + wn*4 + qcol] = s;
            redQ[mloc*16 + wn*4 + qcol] = q;
        }
    }
    __syncthreads();
    if (tid < 128) {
        float s = 0.f;
        #pragma unroll
        for (int i = 0; i < 16; ++i) s += redS[tid*16 + i];
        atomicAdd(&Su[m0c + tid], s);
    } else {
        int m = tid - 128;
        float q = 0.f;
        #pragma unroll
        for (int i = 0; i < 16; ++i) q += redQ[m*16 + i];
        atomicAdd(&Sq[m0c + m], q);
    }
}

// ---------------- final: out_feat = max_k relu(aff4(y4)) ----------------------
__global__ void k_final(float* __restrict__ out) {
    int bs = blockIdx.x;   // 4096
    int c  = threadIdx.x;  // 256
    float sc = g_s4[c], hh = g_t4[c];
    size_t base = (size_t)bs*32*256 + c;
    float mx = 0.f;
    #pragma unroll 8
    for (int pp = 0; pp < 32; ++pp) {
        float v = g_y4[base + (size_t)pp*256];
        mx = fmaxf(mx, fmaxf(fmaf(v, sc, hh), 0.f));
    }
    int b = bs >> 10, sI = bs & 1023;
    out[(((b << 8) + c) << 10) + sI] = mx;
}

// ---------------- launcher ----------------------------------------------------
extern "C" void kernel_launch(void* const* d_in, const int* in_sizes, int n_in,
                              void* d_out, int out_size) {
    const float* p   = (const float*)d_in[0];
    const float* f   = (const float*)d_in[1];
    const float* w1  = (const float*)d_in[2];
    const float* w2  = (const float*)d_in[3];
    const float* b2  = (const float*)d_in[4];
    const float* g2  = (const float*)d_in[5];
    const float* be2 = (const float*)d_in[6];
    const float* w3  = (const float*)d_in[7];
    const float* g3  = (const float*)d_in[8];
    const float* be3 = (const float*)d_in[9];
    const float* w4  = (const float*)d_in[10];
    const float* g4  = (const float*)d_in[11];
    const float* be4 = (const float*)d_in[12];
    float* out = (float*)d_out;

    cudaFuncSetAttribute(k_mma<1>, cudaFuncAttributeMaxDynamicSharedMemorySize, MMA_SMEM);
    cudaFuncSetAttribute(k_mma<2>, cudaFuncAttributeMaxDynamicSharedMemorySize, MMA_SMEM);

    k_zero<<<1, 512>>>();
    k_w21<<<1, 256>>>(w1, w2);
    k_wsplit<<<512, 256>>>(w3, w4);
    k_fps<<<BB, 1024>>>(p, out);                       // cntrd -> d_out[0..12288)
    k_knn<<<BB*NSAMP, 128>>>(p, out);
    k_gconv1<<<MTOT/64, 256>>>(p, f, b2);              // y1 + stats2
    k_params<2><<<2, 256>>>(g2, be2);
    k_c1<<<BB*NSAMP, 256>>>();                         // y1 hi/lo + xm
    k_gemm0<<<dim3(4, 32), 256>>>(w3);                 // h3 = w3a @ xm
    k_mma<1><<<dim3(4, 512), 256, MMA_SMEM>>>();       // y3 + stats3
    k_params<3><<<2, 256>>>(g3, be3);
    k_c3<<<65536, 256>>>();                            // y3 hi/lo
    k_mma<2><<<dim3(2, 512), 256, MMA_SMEM>>>();       // y4 + stats4
    k_params<4><<<2, 256>>>(g4, be4);
    k_final<<<BB*NSAMP, 256>>>(out + BB*NSAMP*3);
}

// round 9
// speedup vs baseline: 2.5374x; 1.2981x over previous
#include <cuda_runtime.h>
#include <cuda_fp16.h>
#include <cstdint>

#define BB 4
#define NN 4096
#define NSAMP 1024
#define KNB 32
#define MTOT (BB*NSAMP*KNB)   // 131072 positions

// ---------------- scratch (device globals; no allocations allowed) ------------
__device__ float g_w21[256*6];
__device__ int   g_knn[MTOT];
__device__ float g_y1[(size_t)MTOT*256];       // conv1 out, [m][c] fp32
__device__ __half g_y1h[(size_t)MTOT*256];     // relu(aff2(y1)) fp16, [m][c]
__device__ float g_xm[256*BB*NSAMP];           // [c][bs]
__device__ float g_h3[512*BB*NSAMP];           // [row][bs]
__device__ float g_y3[(size_t)MTOT*512];       // conv3 out, [n][512] fp32
__device__ __half g_y3h[(size_t)MTOT*512];
__device__ float g_y4[(size_t)MTOT*256];       // conv4 out, [n][256] fp32
__device__ __half g_w3bh[512*256];
__device__ __half g_w4h[256*512];
__device__ float g_sum2[256], g_sq2[256];
__device__ float g_sum3[512], g_sq3[512];
__device__ float g_sum4[256], g_sq4[256];
__device__ float g_s2[256], g_t2[256];
__device__ float g_s3[512], g_t3[512];
__device__ float g_s4[256], g_t4[256];

// ---------------- helpers -----------------------------------------------------
__device__ __forceinline__ uint32_t smem_to_u32(const void* p) {
    uint32_t a;
    asm("{ .reg .u64 t; cvta.to.shared.u64 t, %1; cvt.u32.u64 %0, t; }" : "=r"(a) : "l"(p));
    return a;
}
__device__ __forceinline__ unsigned long long dup2(float a) {
    unsigned int u = __float_as_uint(a);
    return ((unsigned long long)u << 32) | (unsigned long long)u;
}
__device__ __forceinline__ unsigned long long pk64(float a, float b) {
    unsigned long long r;
    asm("mov.b64 %0, {%1,%2};" : "=l"(r) : "f"(a), "f"(b));
    return r;
}
__device__ __forceinline__ void up64(float& a, float& b, unsigned long long v) {
    asm("mov.b64 {%0,%1}, %2;" : "=f"(a), "=f"(b) : "l"(v));
}
__device__ __forceinline__ unsigned long long fma2(unsigned long long a,
                                                   unsigned long long b,
                                                   unsigned long long c) {
    unsigned long long r;
    asm("fma.rn.f32x2 %0, %1, %2, %3;" : "=l"(r) : "l"(a), "l"(b), "l"(c));
    return r;
}
__device__ __forceinline__ unsigned int fmono(float f) {
    unsigned int u = __float_as_uint(f);
    return (u & 0x80000000u) ? ~u : (u | 0x80000000u);
}
__device__ __forceinline__ uint32_t pk2h(__half a, __half b) {
    return ((uint32_t)__half_as_ushort(b) << 16) | (uint32_t)__half_as_ushort(a);
}

#define CP_ASYNC16(dst, src) \
    asm volatile("cp.async.cg.shared.global [%0], [%1], 16;" :: "r"(dst), "l"(src) : "memory")
#define CP_COMMIT() asm volatile("cp.async.commit_group;" ::: "memory")
#define CP_WAIT0() asm volatile("cp.async.wait_group 0;" ::: "memory")
#define CP_WAIT1() asm volatile("cp.async.wait_group 1;" ::: "memory")

__device__ __forceinline__ void ldsm_x4(uint32_t& r0, uint32_t& r1, uint32_t& r2, uint32_t& r3, uint32_t addr) {
    asm volatile("ldmatrix.sync.aligned.m8n8.x4.shared.b16 {%0,%1,%2,%3}, [%4];"
        : "=r"(r0), "=r"(r1), "=r"(r2), "=r"(r3) : "r"(addr));
}
__device__ __forceinline__ void ldsm_x2(uint32_t& r0, uint32_t& r1, uint32_t addr) {
    asm volatile("ldmatrix.sync.aligned.m8n8.x2.shared.b16 {%0,%1}, [%2];"
        : "=r"(r0), "=r"(r1) : "r"(addr));
}
__device__ __forceinline__ void mma16816(float* d, const uint32_t* a, const uint32_t* b) {
    asm volatile("mma.sync.aligned.m16n8k16.row.col.f32.f16.f16.f32 "
        "{%0,%1,%2,%3}, {%4,%5,%6,%7}, {%8,%9}, {%0,%1,%2,%3};"
        : "+f"(d[0]), "+f"(d[1]), "+f"(d[2]), "+f"(d[3])
        : "r"(a[0]), "r"(a[1]), "r"(a[2]), "r"(a[3]), "r"(b[0]), "r"(b[1]));
}

// ---------------- zero stats --------------------------------------------------
__global__ void k_zero() {
    int t = threadIdx.x;  // 512
    if (t < 256) { g_sum2[t]=0.f; g_sq2[t]=0.f; g_sum4[t]=0.f; g_sq4[t]=0.f; }
    g_sum3[t]=0.f; g_sq3[t]=0.f;
}

// ---------------- w21 = w2 @ w1 -----------------------------------------------
__global__ void k_w21(const float* __restrict__ w1, const float* __restrict__ w2) {
    int o = threadIdx.x;
    float acc[6] = {0.f,0.f,0.f,0.f,0.f,0.f};
    for (int c = 0; c < 256; ++c) {
        float w = w2[o*256 + c];
        #pragma unroll
        for (int i = 0; i < 6; ++i) acc[i] = fmaf(w, w1[c*6+i], acc[i]);
    }
    #pragma unroll
    for (int i = 0; i < 6; ++i) g_w21[o*6+i] = acc[i];
}

// ---------------- weight fp16 -------------------------------------------------
__global__ void k_wsplit(const float* __restrict__ w3, const float* __restrict__ w4) {
    int i = blockIdx.x*256 + threadIdx.x;   // 0..131071
    int r = i >> 8, c = i & 255;
    g_w3bh[i] = __float2half(w3[r*512 + 256 + c]);
    g_w4h[i]  = __float2half(w4[i]);
}

// ---------------- FPS: single barrier/iter, all-warp final reduce --------------
__global__ void __launch_bounds__(1024, 1) k_fps(const float* __restrict__ p,
                                                 float* __restrict__ outC) {
    int b = blockIdx.x;
    const float* pb = p + b*NN*3;
    int t = threadIdx.x;
    int lane = t & 31, w = t >> 5;

    float px[4], py[4], pz[4], dm[4];
    #pragma unroll
    for (int j = 0; j < 4; ++j) {
        int i = t + j*1024;
        px[j] = pb[i*3]; py[j] = pb[i*3+1]; pz[j] = pb[i*3+2];
        dm[j] = 1e10f;
    }
    unsigned long long pX01 = pk64(px[0], px[1]), pX23 = pk64(px[2], px[3]);
    unsigned long long pY01 = pk64(py[0], py[1]), pY23 = pk64(py[2], py[3]);
    unsigned long long pZ01 = pk64(pz[0], pz[1]), pZ23 = pk64(pz[2], pz[3]);
    const unsigned long long NEG1 = dup2(-1.0f);

    __shared__ unsigned s_v[2][32];
    __shared__ unsigned s_i[2][32];

    float cx = pb[0], cy = pb[1], cz = pb[2];    // LDG broadcast, all threads
    if (t == 0) {
        float* o = outC + b*NSAMP*3;
        o[0] = cx; o[1] = cy; o[2] = cz;
    }

    for (int it = 0; it < NSAMP; ++it) {
        int buf = it & 1;
        unsigned long long c2x = dup2(cx), c2y = dup2(cy), c2z = dup2(cz);
        unsigned long long tx = fma2(c2x, NEG1, pX01);
        unsigned long long ty = fma2(c2y, NEG1, pY01);
        unsigned long long tz = fma2(c2z, NEG1, pZ01);
        unsigned long long d2 = fma2(tx, tx, 0ull);
        d2 = fma2(ty, ty, d2);
        d2 = fma2(tz, tz, d2);
        float d0, d1; up64(d0, d1, d2);
        tx = fma2(c2x, NEG1, pX23);
        ty = fma2(c2y, NEG1, pY23);
        tz = fma2(c2z, NEG1, pZ23);
        d2 = fma2(tx, tx, 0ull);
        d2 = fma2(ty, ty, d2);
        d2 = fma2(tz, tz, d2);
        float d3, d4; up64(d3, d4, d2);

        dm[0] = fminf(dm[0], d0); dm[1] = fminf(dm[1], d1);
        dm[2] = fminf(dm[2], d3); dm[3] = fminf(dm[3], d4);

        float best = fmaxf(fmaxf(dm[0], dm[1]), fmaxf(dm[2], dm[3]));
        int bi = (dm[0] == best) ? t
               : (dm[1] == best) ? t + 1024
               : (dm[2] == best) ? t + 2048 : t + 3072;

        unsigned mv   = fmono(best);
        unsigned wmax = __reduce_max_sync(0xffffffffu, mv);
        unsigned cand = (mv == wmax) ? (unsigned)bi : 0xffffffffu;
        unsigned widx = __reduce_min_sync(0xffffffffu, cand);
        if (lane == 0) { s_v[buf][w] = wmax; s_i[buf][w] = widx; }
        __syncthreads();

        // every warp computes the block winner (no second barrier; double buffer)
        unsigned mv2 = s_v[buf][lane], id2 = s_i[buf][lane];
        unsigned m2  = __reduce_max_sync(0xffffffffu, mv2);
        unsigned c2v = (mv2 == m2) ? id2 : 0xffffffffu;
        unsigned far = __reduce_min_sync(0xffffffffu, c2v);

        cx = pb[far*3]; cy = pb[far*3+1]; cz = pb[far*3+2];  // LDG broadcast
        if (t == 0 && it + 1 < NSAMP) {
            float* o = outC + (b*NSAMP + it + 1)*3;
            o[0] = cx; o[1] = cy; o[2] = cz;
        }
    }
}

// ---------------- KNN ---------------------------------------------------------
__global__ void k_knn(const float* __restrict__ p, const float* __restrict__ cent) {
    int cid = blockIdx.x;
    int b = cid >> 10;
    const float* pb = p + b*NN*3;
    int t = threadIdx.x;  // 128
    float cx = cent[cid*3], cy = cent[cid*3+1], cz = cent[cid*3+2];
    float cn = cx*cx + cy*cy + cz*cz;
    unsigned long long key[32];
    #pragma unroll
    for (int j = 0; j < 32; ++j) {
        int i = j*128 + t;
        float x = pb[i*3], y = pb[i*3+1], z = pb[i*3+2];
        float pn = x*x + y*y + z*z;
        float dot = fmaf(cx, x, fmaf(cy, y, cz*z));
        float d2  = fmaf(-2.0f, dot, cn + pn);
        key[j] = ((unsigned long long)fmono(d2) << 32) | (unsigned int)i;
    }
    __shared__ unsigned long long s_part[4];
    __shared__ unsigned long long s_prev;
    unsigned long long prev = 0ull;
    int w = t >> 5, lane = t & 31;
    for (int r = 0; r < KNB; ++r) {
        unsigned long long best = ~0ull;
        #pragma unroll
        for (int j = 0; j < 32; ++j) {
            unsigned long long k = key[j];
            if (k > prev && k < best) best = k;
        }
        #pragma unroll
        for (int off = 16; off; off >>= 1) {
            unsigned long long o = __shfl_down_sync(0xffffffffu, best, off);
            if (o < best) best = o;
        }
        if (lane == 0) s_part[w] = best;
        __syncthreads();
        if (t == 0) {
            unsigned long long m = s_part[0];
            #pragma unroll
            for (int i = 1; i < 4; ++i) if (s_part[i] < m) m = s_part[i];
            s_prev = m;
            g_knn[cid*KNB + r] = (int)(m & 0xffffffffull);
        }
        __syncthreads();
        prev = s_prev;
    }
}

// ------- gather + conv(6->256)+bias -> y1 [m][256] + stage-2 stats ------------
__global__ void k_gconv1(const float* __restrict__ p, const float* __restrict__ f,
                         const float* __restrict__ b2) {
    __shared__ float sw[256*6];
    __shared__ float sbb[256];
    __shared__ float sv[64][6];
    int t = threadIdx.x;
    #pragma unroll
    for (int i = 0; i < 6; ++i) sw[t*6+i] = g_w21[t*6+i];
    sbb[t] = b2[t];
    int m0 = blockIdx.x*64;
    if (t < 64) {
        int m = m0 + t;
        int b = m >> 15;
        int idx = g_knn[m];
        const float* pp = p + b*NN*3 + idx*3;
        const float* ff = f + b*3*NN + idx;
        sv[t][0] = pp[0]; sv[t][1] = pp[1]; sv[t][2] = pp[2];
        sv[t][3] = ff[0]; sv[t][4] = ff[NN]; sv[t][5] = ff[2*NN];
    }
    __syncthreads();
    int c = t;
    float w0 = sw[c*6], w1 = sw[c*6+1], w2 = sw[c*6+2];
    float w3 = sw[c*6+3], w4 = sw[c*6+4], w5 = sw[c*6+5];
    float bias = sbb[c];
    float s = 0.f, q = 0.f;
    #pragma unroll 4
    for (int pp = 0; pp < 64; ++pp) {
        float a = bias;
        a = fmaf(w0, sv[pp][0], a); a = fmaf(w1, sv[pp][1], a); a = fmaf(w2, sv[pp][2], a);
        a = fmaf(w3, sv[pp][3], a); a = fmaf(w4, sv[pp][4], a); a = fmaf(w5, sv[pp][5], a);
        g_y1[(size_t)(m0+pp)*256 + c] = a;
        s += a; q = fmaf(a, a, q);
    }
    atomicAdd(&g_sum2[c], s);
    atomicAdd(&g_sq2[c], q);
}

// ---------------- BN params ---------------------------------------------------
template<int STAGE>
__global__ void k_params(const float* __restrict__ g, const float* __restrict__ be) {
    constexpr int C = (STAGE == 3) ? 512 : 256;
    const float* su = (STAGE == 2) ? g_sum2 : (STAGE == 3) ? g_sum3 : g_sum4;
    const float* sq = (STAGE == 2) ? g_sq2  : (STAGE == 3) ? g_sq3  : g_sq4;
    float* sc = (STAGE == 2) ? g_s2 : (STAGE == 3) ? g_s3 : g_s4;
    float* sh = (STAGE == 2) ? g_t2 : (STAGE == 3) ? g_t3 : g_t4;
    int c = blockIdx.x*blockDim.x + threadIdx.x;
    if (c < C) {
        const float inv = 1.0f / (float)MTOT;
        float mean = su[c]*inv;
        float var  = fmaf(-mean, mean, sq[c]*inv);
        float r    = rsqrtf(var + 1e-5f);
        float s    = g[c]*r;
        sc[c] = s;
        sh[c] = fmaf(-mean, s, be[c]);
    }
}

// ---- c1: relu(aff2(y1)) -> fp16 [m][256] + xm [c][bs] ------------------------
__global__ void k_c1() {
    int bs = blockIdx.x;      // 4096
    int c  = threadIdx.x;     // 256
    float sc = g_s2[c], hh = g_t2[c];
    size_t base = (size_t)bs*32*256 + c;
    float mx = 0.f;
    #pragma unroll 8
    for (int pp = 0; pp < 32; ++pp) {
        float v = g_y1[base + (size_t)pp*256];
        float a = fmaxf(fmaf(v, sc, hh), 0.f);
        mx = fmaxf(mx, a);
        g_y1h[base + (size_t)pp*256] = __float2half(a);
    }
    g_xm[c*(BB*NSAMP) + bs] = mx;
}

// ---- c3: relu(aff3(y3)) -> fp16 [n][512] -------------------------------------
__global__ void k_c3() {
    size_t i = (size_t)blockIdx.x*256 + threadIdx.x;   // float4 index (16.7M)
    float4 v = ((const float4*)g_y3)[i];
    int k = ((int)(i & 127)) * 4;
    float a0 = fmaxf(fmaf(v.x, g_s3[k],   g_t3[k]),   0.f);
    float a1 = fmaxf(fmaf(v.y, g_s3[k+1], g_t3[k+1]), 0.f);
    float a2 = fmaxf(fmaf(v.z, g_s3[k+2], g_t3[k+2]), 0.f);
    float a3 = fmaxf(fmaf(v.w, g_s3[k+3], g_t3[k+3]), 0.f);
    ((uint2*)g_y3h)[i] = make_uint2(pk2h(__float2half(a0), __float2half(a1)),
                                   pk2h(__float2half(a2), __float2half(a3)));
}

// ---------------- small fp32 GEMM: h3 = w3[:, :256] @ xm ----------------------
__global__ void __launch_bounds__(256, 2) k_gemm0(const float* __restrict__ A) {
    constexpr int Nn = BB*NSAMP;     // 4096
    constexpr int Kd = 256, lda = 512;
    __shared__ unsigned long long As[16][128];
    __shared__ float Bs[16][128];
    int m0 = blockIdx.x * 128;
    int n0 = blockIdx.y * 128;
    int t  = threadIdx.x;
    int ar  = t & 127, akq = (t >> 7) * 8;
    int bkr = t >> 4,  bnc = (t & 15) * 8;
    int ty = t >> 4, tx = t & 15;
    unsigned long long acc[8][4];
    #pragma unroll
    for (int i = 0; i < 8; ++i)
        #pragma unroll
        for (int j = 0; j < 4; ++j) acc[i][j] = 0ull;
    for (int k0 = 0; k0 < Kd; k0 += 16) {
        const float* ga = A + (size_t)(m0 + ar)*lda + k0 + akq;
        float4 a0 = *(const float4*)ga;
        float4 a1 = *(const float4*)(ga + 4);
        const float* gb = g_xm + (size_t)(k0 + bkr)*Nn + n0 + bnc;
        float4 b0 = *(const float4*)gb;
        float4 b1 = *(const float4*)(gb + 4);
        __syncthreads();
        As[akq+0][ar] = dup2(a0.x); As[akq+1][ar] = dup2(a0.y);
        As[akq+2][ar] = dup2(a0.z); As[akq+3][ar] = dup2(a0.w);
        As[akq+4][ar] = dup2(a1.x); As[akq+5][ar] = dup2(a1.y);
        As[akq+6][ar] = dup2(a1.z); As[akq+7][ar] = dup2(a1.w);
        *(float4*)&Bs[bkr][bnc]     = b0;
        *(float4*)&Bs[bkr][bnc + 4] = b1;
        __syncthreads();
        #pragma unroll
        for (int kk = 0; kk < 16; ++kk) {
            unsigned long long af[8], bf[4];
            const unsigned long long* ap = &As[kk][ty*8];
            #pragma unroll
            for (int i = 0; i < 8; ++i) af[i] = ap[i];
            const unsigned long long* bp = (const unsigned long long*)&Bs[kk][tx*8];
            #pragma unroll
            for (int j = 0; j < 4; ++j) bf[j] = bp[j];
            #pragma unroll
            for (int i = 0; i < 8; ++i)
                #pragma unroll
                for (int j = 0; j < 4; ++j)
                    asm("fma.rn.f32x2 %0, %1, %2, %0;"
                        : "+l"(acc[i][j]) : "l"(af[i]), "l"(bf[j]));
        }
    }
    #pragma unroll
    for (int i = 0; i < 8; ++i) {
        int gr = m0 + ty*8 + i;
        float out[8];
        #pragma unroll
        for (int j = 0; j < 4; ++j) {
            out[2*j]   = __uint_as_float((unsigned int)(acc[i][j] & 0xffffffffull));
            out[2*j+1] = __uint_as_float((unsigned int)(acc[i][j] >> 32));
        }
        float4* cp = (float4*)(g_h3 + (size_t)gr*Nn + n0 + tx*8);
        cp[0] = make_float4(out[0], out[1], out[2], out[3]);
        cp[1] = make_float4(out[4], out[5], out[6], out[7]);
    }
}

// ---------------- mma.sync fp16 GEMM (single pass), CTA 128x256 ---------------
// MODE 1: y3[n][512] = w3b(512x256) @ x1^T  + h3-broadcast, stats3
// MODE 2: y4[n][256] = w4 (256x512) @ x3^T,                 stats4
// 8 warps (2x4), warp tile 64x64, K-chunk 32, 3-stage cp.async.
// Stage: A[0,10240) B[10240,30720). Smem row stride 80B.
#define STG_BYTES 30720
#define MMA_SMEM  (3*STG_BYTES)     // 92160

template<int MODE>
__device__ __forceinline__ void mma_issue(uint32_t sbase, int st, int k0,
                                          int m0c, int n0c, int tid) {
    constexpr int Kd = (MODE == 1) ? 256 : 512;
    const __half* __restrict__ Ah = (MODE == 1) ? g_w3bh : g_w4h;
    const __half* __restrict__ Bh = (MODE == 1) ? g_y1h : g_y3h;
    uint32_t base = sbase + st*STG_BYTES;
    #pragma unroll
    for (int i = 0; i < 2; ++i) {            // A: 128 rows x 4 x 16B
        int u = tid + i*256;                 // 0..511
        int r = u >> 2, q = u & 3;
        const __half* src = Ah + (size_t)(m0c + r)*Kd + k0 + q*8;
        CP_ASYNC16(base + r*80 + q*16, src);
    }
    #pragma unroll
    for (int i = 0; i < 4; ++i) {            // B: 256 rows x 4 x 16B
        int u = tid + i*256;                 // 0..1023
        int r = u >> 2, q = u & 3;
        const __half* src = Bh + (size_t)(n0c + r)*Kd + k0 + q*8;
        CP_ASYNC16(base + 10240 + r*80 + q*16, src);
    }
}

template<int MODE>
__global__ void __launch_bounds__(256) k_mma() {
    constexpr int Kd = (MODE == 1) ? 256 : 512;
    constexpr int KT = Kd / 32;
    constexpr int Ms = (MODE == 1) ? 512 : 256;    // C row stride
    float* __restrict__ C  = (MODE == 1) ? g_y3 : g_y4;
    float* __restrict__ Su = (MODE == 1) ? g_sum3 : g_sum4;
    float* __restrict__ Sq = (MODE == 1) ? g_sq3 : g_sq4;

    extern __shared__ char smem[];
    uint32_t sb = smem_to_u32(smem);
    int tid = threadIdx.x, lane = tid & 31, wid = tid >> 5;
    int wm = wid >> 2, wn = wid & 3;               // 2 x 4 warps
    int m0c = blockIdx.x * 128, n0c = blockIdx.y * 256;

    float acc[4][8][4];
    #pragma unroll
    for (int a = 0; a < 4; ++a)
        #pragma unroll
        for (int b = 0; b < 8; ++b)
            #pragma unroll
            for (int c = 0; c < 4; ++c) acc[a][b][c] = 0.f;

    int sel = lane >> 3;
    uint32_t aRow = (uint32_t)((sel & 1)*8 + (lane & 7));
    uint32_t aCol = (uint32_t)((sel >> 1) * 16);
    uint32_t bRowB = (uint32_t)(wn*64 + (lane & 7));
    uint32_t bCol = (uint32_t)(((lane >> 3) & 1) * 16);

    mma_issue<MODE>(sb, 0, 0,  m0c, n0c, tid); CP_COMMIT();
    mma_issue<MODE>(sb, 1, 32, m0c, n0c, tid); CP_COMMIT();

    for (int kt = 0; kt < KT; ++kt) {
        if (kt == KT-1) { CP_WAIT0(); } else { CP_WAIT1(); }
        __syncthreads();
        if (kt + 2 < KT) {
            mma_issue<MODE>(sb, (kt+2)%3, (kt+2)*32, m0c, n0c, tid);
            CP_COMMIT();
        }
        uint32_t sA = sb + (kt%3)*STG_BYTES;
        uint32_t sBB = sA + 10240;
        #pragma unroll
        for (int ks = 0; ks < 2; ++ks) {
            uint32_t kOff = (uint32_t)(ks*32);
            uint32_t ah[4][4], bf[8][2];
            #pragma unroll
            for (int mt = 0; mt < 4; ++mt)
                ldsm_x4(ah[mt][0], ah[mt][1], ah[mt][2], ah[mt][3],
                        sA + (uint32_t)(wm*64 + mt*16 + aRow)*80 + kOff + aCol);
            #pragma unroll
            for (int nt = 0; nt < 8; ++nt)
                ldsm_x2(bf[nt][0], bf[nt][1],
                        sBB + (bRowB + (uint32_t)(nt*8))*80 + kOff + bCol);
            #pragma unroll
            for (int mt = 0; mt < 4; ++mt)
                #pragma unroll
                for (int nt = 0; nt < 8; ++nt)
                    mma16816(acc[mt][nt], ah[mt], bf[nt]);
        }
    }

    // ---------------- epilogue: store C (+h3), fused BN stats ----------------
    __syncthreads();                       // smem reuse for reduction
    float* redS = (float*)smem;            // [128][16]
    float* redQ = (float*)(smem + 8192);
    int qrow = lane >> 2, qcol = lane & 3;

    #pragma unroll
    for (int mt = 0; mt < 4; ++mt) {
        #pragma unroll
        for (int hf = 0; hf < 2; ++hf) {
            int mloc = wm*64 + mt*16 + hf*8 + qrow;
            int mg = m0c + mloc;
            float h3a = 0.f, h3b = 0.f;
            if (MODE == 1) {
                int gidx = (n0c >> 5) + wn*2;
                h3a = g_h3[(size_t)mg*(BB*NSAMP) + gidx];
                h3b = g_h3[(size_t)mg*(BB*NSAMP) + gidx + 1];
            }
            float s = 0.f, q = 0.f;
            #pragma unroll
            for (int nt = 0; nt < 8; ++nt) {
                float h3v = (nt < 4) ? h3a : h3b;
                #pragma unroll
                for (int j = 0; j < 2; ++j) {
                    float v = acc[mt][nt][hf*2 + j] + h3v;
                    int ng = n0c + wn*64 + nt*8 + qcol*2 + j;
                    C[(size_t)ng*Ms + mg] = v;
                    s += v; q = fmaf(v, v, q);
                }
            }
            redS[mloc*16 + wn*4 + qcol] = s;
            redQ[mloc*16 + wn*4 + qcol] = q;
        }
    }
    __syncthreads();
    if (tid < 128) {
        float s = 0.f;
        #pragma unroll
        for (int i = 0; i < 16; ++i) s += redS[tid*16 + i];
        atomicAdd(&Su[m0c + tid], s);
    } else {
        int m = tid - 128;
        float q = 0.f;
        #pragma unroll
        for (int i = 0; i < 16; ++i) q += redQ[m*16 + i];
        atomicAdd(&Sq[m0c + m], q);
    }
}

// ---------------- final: out_feat = max_k relu(aff4(y4)) ----------------------
__global__ void k_final(float* __restrict__ out) {
    int bs = blockIdx.x;   // 4096
    int c  = threadIdx.x;  // 256
    float sc = g_s4[c], hh = g_t4[c];
    size_t base = (size_t)bs*32*256 + c;
    float mx = 0.f;
    #pragma unroll 8
    for (int pp = 0; pp < 32; ++pp) {
        float v = g_y4[base + (size_t)pp*256];
        mx = fmaxf(mx, fmaxf(fmaf(v, sc, hh), 0.f));
    }
    int b = bs >> 10, sI = bs & 1023;
    out[(((b << 8) + c) << 10) + sI] = mx;
}

// ---------------- launcher ----------------------------------------------------
extern "C" void kernel_launch(void* const* d_in, const int* in_sizes, int n_in,
                              void* d_out, int out_size) {
    const float* p   = (const float*)d_in[0];
    const float* f   = (const float*)d_in[1];
    const float* w1  = (const float*)d_in[2];
    const float* w2  = (const float*)d_in[3];
    const float* b2  = (const float*)d_in[4];
    const float* g2  = (const float*)d_in[5];
    const float* be2 = (const float*)d_in[6];
    const float* w3  = (const float*)d_in[7];
    const float* g3  = (const float*)d_in[8];
    const float* be3 = (const float*)d_in[9];
    const float* w4  = (const float*)d_in[10];
    const float* g4  = (const float*)d_in[11];
    const float* be4 = (const float*)d_in[12];
    float* out = (float*)d_out;

    cudaFuncSetAttribute(k_mma<1>, cudaFuncAttributeMaxDynamicSharedMemorySize, MMA_SMEM);
    cudaFuncSetAttribute(k_mma<2>, cudaFuncAttributeMaxDynamicSharedMemorySize, MMA_SMEM);

    k_zero<<<1, 512>>>();
    k_w21<<<1, 256>>>(w1, w2);
    k_wsplit<<<512, 256>>>(w3, w4);
    k_fps<<<BB, 1024>>>(p, out);                       // cntrd -> d_out[0..12288)
    k_knn<<<BB*NSAMP, 128>>>(p, out);
    k_gconv1<<<MTOT/64, 256>>>(p, f, b2);              // y1 + stats2
    k_params<2><<<2, 256>>>(g2, be2);
    k_c1<<<BB*NSAMP, 256>>>();                         // y1 fp16 + xm
    k_gemm0<<<dim3(4, 32), 256>>>(w3);                 // h3 = w3a @ xm
    k_mma<1><<<dim3(4, 512), 256, MMA_SMEM>>>();       // y3 + stats3
    k_params<3><<<2, 256>>>(g3, be3);
    k_c3<<<65536, 256>>>();                            // y3 fp16
    k_mma<2><<<dim3(2, 512), 256, MMA_SMEM>>>();       // y4 + stats4
    k_params<4><<<2, 256>>>(g4, be4);
    k_final<<<BB*NSAMP, 256>>>(out + BB*NSAMP*3);
}

// round 10
// speedup vs baseline: 2.8745x; 1.1328x over previous
#include <cuda_runtime.h>
#include <cuda_fp16.h>
#include <cstdint>

#define BB 4
#define NN 4096
#define NSAMP 1024
#define KNB 32
#define MTOT (BB*NSAMP*KNB)   // 131072 positions

// ---------------- scratch (device globals; no allocations allowed) ------------
__device__ float g_w21[256*6];
__device__ int   g_knn[MTOT];
__device__ __half g_y1h[(size_t)MTOT*256];     // conv1 out RAW fp16, [m][c]
__device__ __half g_y1a[(size_t)MTOT*256];     // relu(aff2(y1)) fp16, [m][c]
__device__ float g_xm[256*BB*NSAMP];           // [c][bs]
__device__ float g_h3[512*BB*NSAMP];           // [row][bs]
__device__ __half g_y3h[(size_t)MTOT*512];     // conv3 out RAW fp16, [n][512]
__device__ __half g_y3a[(size_t)MTOT*512];     // relu(aff3(y3)) fp16
__device__ float g_y4m[256*BB*NSAMP];          // max_k of RAW y4, [c][bs]
__device__ __half g_w3bh[512*256];
__device__ __half g_w4h[256*512];
__device__ float g_sum2[256], g_sq2[256];
__device__ float g_sum3[512], g_sq3[512];
__device__ float g_sum4[256], g_sq4[256];
__device__ float g_s2[256], g_t2[256];
__device__ float g_s3[512], g_t3[512];
__device__ float g_s4[256], g_t4[256];

// ---------------- helpers -----------------------------------------------------
__device__ __forceinline__ uint32_t smem_to_u32(const void* p) {
    uint32_t a;
    asm("{ .reg .u64 t; cvta.to.shared.u64 t, %1; cvt.u32.u64 %0, t; }" : "=r"(a) : "l"(p));
    return a;
}
__device__ __forceinline__ unsigned long long dup2(float a) {
    unsigned int u = __float_as_uint(a);
    return ((unsigned long long)u << 32) | (unsigned long long)u;
}
__device__ __forceinline__ unsigned long long pk64(float a, float b) {
    unsigned long long r;
    asm("mov.b64 %0, {%1,%2};" : "=l"(r) : "f"(a), "f"(b));
    return r;
}
__device__ __forceinline__ void up64(float& a, float& b, unsigned long long v) {
    asm("mov.b64 {%0,%1}, %2;" : "=f"(a), "=f"(b) : "l"(v));
}
__device__ __forceinline__ unsigned long long fma2(unsigned long long a,
                                                   unsigned long long b,
                                                   unsigned long long c) {
    unsigned long long r;
    asm("fma.rn.f32x2 %0, %1, %2, %3;" : "=l"(r) : "l"(a), "l"(b), "l"(c));
    return r;
}
__device__ __forceinline__ unsigned int fmono(float f) {
    unsigned int u = __float_as_uint(f);
    return (u & 0x80000000u) ? ~u : (u | 0x80000000u);
}
__device__ __forceinline__ uint32_t pk2h(__half a, __half b) {
    return ((uint32_t)__half_as_ushort(b) << 16) | (uint32_t)__half_as_ushort(a);
}

#define CP_ASYNC16(dst, src) \
    asm volatile("cp.async.cg.shared.global [%0], [%1], 16;" :: "r"(dst), "l"(src) : "memory")
#define CP_COMMIT() asm volatile("cp.async.commit_group;" ::: "memory")
#define CP_WAIT0() asm volatile("cp.async.wait_group 0;" ::: "memory")
#define CP_WAIT1() asm volatile("cp.async.wait_group 1;" ::: "memory")

__device__ __forceinline__ void ldsm_x4(uint32_t& r0, uint32_t& r1, uint32_t& r2, uint32_t& r3, uint32_t addr) {
    asm volatile("ldmatrix.sync.aligned.m8n8.x4.shared.b16 {%0,%1,%2,%3}, [%4];"
        : "=r"(r0), "=r"(r1), "=r"(r2), "=r"(r3) : "r"(addr));
}
__device__ __forceinline__ void ldsm_x2(uint32_t& r0, uint32_t& r1, uint32_t addr) {
    asm volatile("ldmatrix.sync.aligned.m8n8.x2.shared.b16 {%0,%1}, [%2];"
        : "=r"(r0), "=r"(r1) : "r"(addr));
}
__device__ __forceinline__ void mma16816(float* d, const uint32_t* a, const uint32_t* b) {
    asm volatile("mma.sync.aligned.m16n8k16.row.col.f32.f16.f16.f32 "
        "{%0,%1,%2,%3}, {%4,%5,%6,%7}, {%8,%9}, {%0,%1,%2,%3};"
        : "+f"(d[0]), "+f"(d[1]), "+f"(d[2]), "+f"(d[3])
        : "r"(a[0]), "r"(a[1]), "r"(a[2]), "r"(a[3]), "r"(b[0]), "r"(b[1]));
}

// ---------------- zero stats --------------------------------------------------
__global__ void k_zero() {
    int t = threadIdx.x;  // 512
    if (t < 256) { g_sum2[t]=0.f; g_sq2[t]=0.f; g_sum4[t]=0.f; g_sq4[t]=0.f; }
    g_sum3[t]=0.f; g_sq3[t]=0.f;
}

// ---------------- w21 = w2 @ w1 -----------------------------------------------
__global__ void k_w21(const float* __restrict__ w1, const float* __restrict__ w2) {
    int o = threadIdx.x;
    float acc[6] = {0.f,0.f,0.f,0.f,0.f,0.f};
    for (int c = 0; c < 256; ++c) {
        float w = w2[o*256 + c];
        #pragma unroll
        for (int i = 0; i < 6; ++i) acc[i] = fmaf(w, w1[c*6+i], acc[i]);
    }
    #pragma unroll
    for (int i = 0; i < 6; ++i) g_w21[o*6+i] = acc[i];
}

// ---------------- weight fp16 -------------------------------------------------
__global__ void k_wsplit(const float* __restrict__ w3, const float* __restrict__ w4) {
    int i = blockIdx.x*256 + threadIdx.x;   // 0..131071
    int r = i >> 8, c = i & 255;
    g_w3bh[i] = __float2half(w3[r*512 + 256 + c]);
    g_w4h[i]  = __float2half(w4[i]);
}

// ---------------- FPS: 512 thr x 8 pts, single barrier/iter -------------------
__global__ void __launch_bounds__(512, 1) k_fps(const float* __restrict__ p,
                                                float* __restrict__ outC) {
    int b = blockIdx.x;
    const float* pb = p + b*NN*3;
    int t = threadIdx.x;
    int lane = t & 31, w = t >> 5;        // 16 warps

    float dm[8];
    unsigned long long pX[4], pY[4], pZ[4];
    #pragma unroll
    for (int j = 0; j < 4; ++j) {
        int i0 = t + (2*j)*512, i1 = t + (2*j+1)*512;
        pX[j] = pk64(pb[i0*3],   pb[i1*3]);
        pY[j] = pk64(pb[i0*3+1], pb[i1*3+1]);
        pZ[j] = pk64(pb[i0*3+2], pb[i1*3+2]);
        dm[2*j] = 1e10f; dm[2*j+1] = 1e10f;
    }
    const unsigned long long NEG1 = dup2(-1.0f);

    __shared__ unsigned s_v[2][16];
    __shared__ unsigned s_i[2][16];

    float cx = pb[0], cy = pb[1], cz = pb[2];
    if (t == 0) {
        float* o = outC + b*NSAMP*3;
        o[0] = cx; o[1] = cy; o[2] = cz;
    }

    for (int it = 0; it < NSAMP; ++it) {
        int buf = it & 1;
        unsigned long long c2x = dup2(cx), c2y = dup2(cy), c2z = dup2(cz);
        #pragma unroll
        for (int j = 0; j < 4; ++j) {
            unsigned long long tx = fma2(c2x, NEG1, pX[j]);
            unsigned long long ty = fma2(c2y, NEG1, pY[j]);
            unsigned long long tz = fma2(c2z, NEG1, pZ[j]);
            unsigned long long d2 = fma2(tx, tx, 0ull);
            d2 = fma2(ty, ty, d2);
            d2 = fma2(tz, tz, d2);
            float da, db; up64(da, db, d2);
            dm[2*j]   = fminf(dm[2*j],   da);
            dm[2*j+1] = fminf(dm[2*j+1], db);
        }

        float best = dm[0];
        #pragma unroll
        for (int j = 1; j < 8; ++j) best = fmaxf(best, dm[j]);
        int bi = t + 7*512;
        #pragma unroll
        for (int j = 6; j >= 0; --j) if (dm[j] == best) bi = t + j*512;

        unsigned mv   = fmono(best);
        unsigned wmax = __reduce_max_sync(0xffffffffu, mv);
        unsigned cand = (mv == wmax) ? (unsigned)bi : 0xffffffffu;
        unsigned widx = __reduce_min_sync(0xffffffffu, cand);
        if (lane == 0) { s_v[buf][w] = wmax; s_i[buf][w] = widx; }
        __syncthreads();

        unsigned mv2 = (lane < 16) ? s_v[buf][lane] : 0u;
        unsigned id2 = (lane < 16) ? s_i[buf][lane] : 0xffffffffu;
        unsigned m2  = __reduce_max_sync(0xffffffffu, mv2);
        unsigned c2v = (mv2 == m2) ? id2 : 0xffffffffu;
        unsigned far = __reduce_min_sync(0xffffffffu, c2v);

        cx = pb[far*3]; cy = pb[far*3+1]; cz = pb[far*3+2];
        if (t == 0 && it + 1 < NSAMP) {
            float* o = outC + (b*NSAMP + it + 1)*3;
            o[0] = cx; o[1] = cy; o[2] = cz;
        }
    }
}

// ---------------- KNN ---------------------------------------------------------
__global__ void k_knn(const float* __restrict__ p, const float* __restrict__ cent) {
    int cid = blockIdx.x;
    int b = cid >> 10;
    const float* pb = p + b*NN*3;
    int t = threadIdx.x;  // 128
    float cx = cent[cid*3], cy = cent[cid*3+1], cz = cent[cid*3+2];
    float cn = cx*cx + cy*cy + cz*cz;
    unsigned long long key[32];
    #pragma unroll
    for (int j = 0; j < 32; ++j) {
        int i = j*128 + t;
        float x = pb[i*3], y = pb[i*3+1], z = pb[i*3+2];
        float pn = x*x + y*y + z*z;
        float dot = fmaf(cx, x, fmaf(cy, y, cz*z));
        float d2  = fmaf(-2.0f, dot, cn + pn);
        key[j] = ((unsigned long long)fmono(d2) << 32) | (unsigned int)i;
    }
    __shared__ unsigned long long s_part[4];
    __shared__ unsigned long long s_prev;
    unsigned long long prev = 0ull;
    int w = t >> 5, lane = t & 31;
    for (int r = 0; r < KNB; ++r) {
        unsigned long long best = ~0ull;
        #pragma unroll
        for (int j = 0; j < 32; ++j) {
            unsigned long long k = key[j];
            if (k > prev && k < best) best = k;
        }
        #pragma unroll
        for (int off = 16; off; off >>= 1) {
            unsigned long long o = __shfl_down_sync(0xffffffffu, best, off);
            if (o < best) best = o;
        }
        if (lane == 0) s_part[w] = best;
        __syncthreads();
        if (t == 0) {
            unsigned long long m = s_part[0];
            #pragma unroll
            for (int i = 1; i < 4; ++i) if (s_part[i] < m) m = s_part[i];
            s_prev = m;
            g_knn[cid*KNB + r] = (int)(m & 0xffffffffull);
        }
        __syncthreads();
        prev = s_prev;
    }
}

// ------- gather + conv(6->256)+bias -> y1h RAW fp16 [m][256] + stats2 ---------
__global__ void k_gconv1(const float* __restrict__ p, const float* __restrict__ f,
                         const float* __restrict__ b2) {
    __shared__ float sw[256*6];
    __shared__ float sbb[256];
    __shared__ float sv[64][6];
    int t = threadIdx.x;
    #pragma unroll
    for (int i = 0; i < 6; ++i) sw[t*6+i] = g_w21[t*6+i];
    sbb[t] = b2[t];
    int m0 = blockIdx.x*64;
    if (t < 64) {
        int m = m0 + t;
        int b = m >> 15;
        int idx = g_knn[m];
        const float* pp = p + b*NN*3 + idx*3;
        const float* ff = f + b*3*NN + idx;
        sv[t][0] = pp[0]; sv[t][1] = pp[1]; sv[t][2] = pp[2];
        sv[t][3] = ff[0]; sv[t][4] = ff[NN]; sv[t][5] = ff[2*NN];
    }
    __syncthreads();
    int c = t;
    float w0 = sw[c*6], w1 = sw[c*6+1], w2 = sw[c*6+2];
    float w3 = sw[c*6+3], w4 = sw[c*6+4], w5 = sw[c*6+5];
    float bias = sbb[c];
    float s = 0.f, q = 0.f;
    #pragma unroll 4
    for (int pp = 0; pp < 64; ++pp) {
        float a = bias;
        a = fmaf(w0, sv[pp][0], a); a = fmaf(w1, sv[pp][1], a); a = fmaf(w2, sv[pp][2], a);
        a = fmaf(w3, sv[pp][3], a); a = fmaf(w4, sv[pp][4], a); a = fmaf(w5, sv[pp][5], a);
        g_y1h[(size_t)(m0+pp)*256 + c] = __float2half(a);
        s += a; q = fmaf(a, a, q);
    }
    atomicAdd(&g_sum2[c], s);
    atomicAdd(&g_sq2[c], q);
}

// ---------------- BN params ---------------------------------------------------
template<int STAGE>
__global__ void k_params(const float* __restrict__ g, const float* __restrict__ be) {
    constexpr int C = (STAGE == 3) ? 512 : 256;
    const float* su = (STAGE == 2) ? g_sum2 : (STAGE == 3) ? g_sum3 : g_sum4;
    const float* sq = (STAGE == 2) ? g_sq2  : (STAGE == 3) ? g_sq3  : g_sq4;
    float* sc = (STAGE == 2) ? g_s2 : (STAGE == 3) ? g_s3 : g_s4;
    float* sh = (STAGE == 2) ? g_t2 : (STAGE == 3) ? g_t3 : g_t4;
    int c = blockIdx.x*blockDim.x + threadIdx.x;
    if (c < C) {
        const float inv = 1.0f / (float)MTOT;
        float mean = su[c]*inv;
        float var  = fmaf(-mean, mean, sq[c]*inv);
        float r    = rsqrtf(var + 1e-5f);
        float s    = g[c]*r;
        sc[c] = s;
        sh[c] = fmaf(-mean, s, be[c]);
    }
}

// ---- c1: relu(aff2(y1h)) -> fp16 [m][256] + xm [c][bs] -----------------------
__global__ void k_c1() {
    int bs = blockIdx.x;      // 4096
    int c  = threadIdx.x;     // 256
    float sc = g_s2[c], hh = g_t2[c];
    size_t base = (size_t)bs*32*256 + c;
    float mx = 0.f;
    #pragma unroll 8
    for (int pp = 0; pp < 32; ++pp) {
        float v = __half2float(g_y1h[base + (size_t)pp*256]);
        float a = fmaxf(fmaf(v, sc, hh), 0.f);
        mx = fmaxf(mx, a);
        g_y1a[base + (size_t)pp*256] = __float2half(a);
    }
    g_xm[c*(BB*NSAMP) + bs] = mx;
}

// ---- c3: relu(aff3(y3h)) -> fp16 [n][512] ------------------------------------
__global__ void k_c3() {
    size_t i = (size_t)blockIdx.x*256 + threadIdx.x;   // uint2 index (16.7M)
    uint2 r = ((const uint2*)g_y3h)[i];
    int k = ((int)(i & 127)) * 4;
    __half2 v01 = *(__half2*)&r.x;
    __half2 v23 = *(__half2*)&r.y;
    float a0 = fmaxf(fmaf(__low2float(v01),  g_s3[k],   g_t3[k]),   0.f);
    float a1 = fmaxf(fmaf(__high2float(v01), g_s3[k+1], g_t3[k+1]), 0.f);
    float a2 = fmaxf(fmaf(__low2float(v23),  g_s3[k+2], g_t3[k+2]), 0.f);
    float a3 = fmaxf(fmaf(__high2float(v23), g_s3[k+3], g_t3[k+3]), 0.f);
    ((uint2*)g_y3a)[i] = make_uint2(pk2h(__float2half(a0), __float2half(a1)),
                                   pk2h(__float2half(a2), __float2half(a3)));
}

// ---------------- small fp32 GEMM: h3 = w3[:, :256] @ xm ----------------------
__global__ void __launch_bounds__(256, 2) k_gemm0(const float* __restrict__ A) {
    constexpr int Nn = BB*NSAMP;     // 4096
    constexpr int Kd = 256, lda = 512;
    __shared__ unsigned long long As[16][128];
    __shared__ float Bs[16][128];
    int m0 = blockIdx.x * 128;
    int n0 = blockIdx.y * 128;
    int t  = threadIdx.x;
    int ar  = t & 127, akq = (t >> 7) * 8;
    int bkr = t >> 4,  bnc = (t & 15) * 8;
    int ty = t >> 4, tx = t & 15;
    unsigned long long acc[8][4];
    #pragma unroll
    for (int i = 0; i < 8; ++i)
        #pragma unroll
        for (int j = 0; j < 4; ++j) acc[i][j] = 0ull;
    for (int k0 = 0; k0 < Kd; k0 += 16) {
        const float* ga = A + (size_t)(m0 + ar)*lda + k0 + akq;
        float4 a0 = *(const float4*)ga;
        float4 a1 = *(const float4*)(ga + 4);
        const float* gb = g_xm + (size_t)(k0 + bkr)*Nn + n0 + bnc;
        float4 b0 = *(const float4*)gb;
        float4 b1 = *(const float4*)(gb + 4);
        __syncthreads();
        As[akq+0][ar] = dup2(a0.x); As[akq+1][ar] = dup2(a0.y);
        As[akq+2][ar] = dup2(a0.z); As[akq+3][ar] = dup2(a0.w);
        As[akq+4][ar] = dup2(a1.x); As[akq+5][ar] = dup2(a1.y);
        As[akq+6][ar] = dup2(a1.z); As[akq+7][ar] = dup2(a1.w);
        *(float4*)&Bs[bkr][bnc]     = b0;
        *(float4*)&Bs[bkr][bnc + 4] = b1;
        __syncthreads();
        #pragma unroll
        for (int kk = 0; kk < 16; ++kk) {
            unsigned long long af[8], bf[4];
            const unsigned long long* ap = &As[kk][ty*8];
            #pragma unroll
            for (int i = 0; i < 8; ++i) af[i] = ap[i];
            const unsigned long long* bp = (const unsigned long long*)&Bs[kk][tx*8];
            #pragma unroll
            for (int j = 0; j < 4; ++j) bf[j] = bp[j];
            #pragma unroll
            for (int i = 0; i < 8; ++i)
                #pragma unroll
                for (int j = 0; j < 4; ++j)
                    asm("fma.rn.f32x2 %0, %1, %2, %0;"
                        : "+l"(acc[i][j]) : "l"(af[i]), "l"(bf[j]));
        }
    }
    #pragma unroll
    for (int i = 0; i < 8; ++i) {
        int gr = m0 + ty*8 + i;
        float out[8];
        #pragma unroll
        for (int j = 0; j < 4; ++j) {
            out[2*j]   = __uint_as_float((unsigned int)(acc[i][j] & 0xffffffffull));
            out[2*j+1] = __uint_as_float((unsigned int)(acc[i][j] >> 32));
        }
        float4* cp = (float4*)(g_h3 + (size_t)gr*Nn + n0 + tx*8);
        cp[0] = make_float4(out[0], out[1], out[2], out[3]);
        cp[1] = make_float4(out[4], out[5], out[6], out[7]);
    }
}

// ---------------- mma.sync fp16 GEMM (single pass), CTA 128x256 ---------------
// MODE 1: y3h[n][512] = fp16(w3b @ y1a^T + h3), stats3   (smem-transposed store)
// MODE 2: y4max[c][bs] = max_k (w4 @ y3a^T), stats4      (no bulk store)
// 8 warps (2x4), warp tile 64x64, K-chunk 32, 3-stage cp.async.
#define STG_BYTES 30720
#define MMA_SMEM  92160     // 3 stages; epilogue reuses 64KB transpose + 16KB red

template<int MODE>
__device__ __forceinline__ void mma_issue(uint32_t sbase, int st, int k0,
                                          int m0c, int n0c, int tid) {
    constexpr int Kd = (MODE == 1) ? 256 : 512;
    const __half* __restrict__ Ah = (MODE == 1) ? g_w3bh : g_w4h;
    const __half* __restrict__ Bh = (MODE == 1) ? g_y1a : g_y3a;
    uint32_t base = sbase + st*STG_BYTES;
    #pragma unroll
    for (int i = 0; i < 2; ++i) {            // A: 128 rows x 4 x 16B
        int u = tid + i*256;
        int r = u >> 2, q = u & 3;
        const __half* src = Ah + (size_t)(m0c + r)*Kd + k0 + q*8;
        CP_ASYNC16(base + r*80 + q*16, src);
    }
    #pragma unroll
    for (int i = 0; i < 4; ++i) {            // B: 256 rows x 4 x 16B
        int u = tid + i*256;
        int r = u >> 2, q = u & 3;
        const __half* src = Bh + (size_t)(n0c + r)*Kd + k0 + q*8;
        CP_ASYNC16(base + 10240 + r*80 + q*16, src);
    }
}

template<int MODE>
__global__ void __launch_bounds__(256) k_mma() {
    constexpr int Kd = (MODE == 1) ? 256 : 512;
    constexpr int KT = Kd / 32;
    float* __restrict__ Su = (MODE == 1) ? g_sum3 : g_sum4;
    float* __restrict__ Sq = (MODE == 1) ? g_sq3 : g_sq4;

    extern __shared__ char smem[];
    uint32_t sb = smem_to_u32(smem);
    int tid = threadIdx.x, lane = tid & 31, wid = tid >> 5;
    int wm = wid >> 2, wn = wid & 3;               // 2 x 4 warps
    int m0c = blockIdx.x * 128, n0c = blockIdx.y * 256;

    float acc[4][8][4];
    #pragma unroll
    for (int a = 0; a < 4; ++a)
        #pragma unroll
        for (int b = 0; b < 8; ++b)
            #pragma unroll
            for (int c = 0; c < 4; ++c) acc[a][b][c] = 0.f;

    int sel = lane >> 3;
    uint32_t aRow = (uint32_t)((sel & 1)*8 + (lane & 7));
    uint32_t aCol = (uint32_t)((sel >> 1) * 16);
    uint32_t bRowB = (uint32_t)(wn*64 + (lane & 7));
    uint32_t bCol = (uint32_t)(((lane >> 3) & 1) * 16);

    mma_issue<MODE>(sb, 0, 0,  m0c, n0c, tid); CP_COMMIT();
    mma_issue<MODE>(sb, 1, 32, m0c, n0c, tid); CP_COMMIT();

    for (int kt = 0; kt < KT; ++kt) {
        if (kt == KT-1) { CP_WAIT0(); } else { CP_WAIT1(); }
        __syncthreads();
        if (kt + 2 < KT) {
            mma_issue<MODE>(sb, (kt+2)%3, (kt+2)*32, m0c, n0c, tid);
            CP_COMMIT();
        }
        uint32_t sA = sb + (kt%3)*STG_BYTES;
        uint32_t sBB = sA + 10240;
        #pragma unroll
        for (int ks = 0; ks < 2; ++ks) {
            uint32_t kOff = (uint32_t)(ks*32);
            uint32_t ah[4][4], bf[8][2];
            #pragma unroll
            for (int mt = 0; mt < 4; ++mt)
                ldsm_x4(ah[mt][0], ah[mt][1], ah[mt][2], ah[mt][3],
                        sA + (uint32_t)(wm*64 + mt*16 + aRow)*80 + kOff + aCol);
            #pragma unroll
            for (int nt = 0; nt < 8; ++nt)
                ldsm_x2(bf[nt][0], bf[nt][1],
                        sBB + (bRowB + (uint32_t)(nt*8))*80 + kOff + bCol);
            #pragma unroll
            for (int mt = 0; mt < 4; ++mt)
                #pragma unroll
                for (int nt = 0; nt < 8; ++nt)
                    mma16816(acc[mt][nt], ah[mt], bf[nt]);
        }
    }

    // ---------------- epilogue ------------------------------------------------
    __syncthreads();
    __half* st = (__half*)smem;              // 256 x 128 halves (64KB), MODE 1
    float* redS = (float*)(smem + 65536);    // [128][16]
    float* redQ = (float*)(smem + 73728);
    int qrow = lane >> 2, qcol = lane & 3;

    #pragma unroll
    for (int mt = 0; mt < 4; ++mt) {
        #pragma unroll
        for (int hf = 0; hf < 2; ++hf) {
            int mloc = wm*64 + mt*16 + hf*8 + qrow;
            int mg = m0c + mloc;
            float h3a = 0.f, h3b = 0.f;
            if (MODE == 1) {
                int gidx = (n0c >> 5) + wn*2;
                h3a = g_h3[(size_t)mg*(BB*NSAMP) + gidx];
                h3b = g_h3[(size_t)mg*(BB*NSAMP) + gidx + 1];
            }
            float s = 0.f, q = 0.f;
            float mx0 = -1e30f, mx1 = -1e30f;
            #pragma unroll
            for (int nt = 0; nt < 8; ++nt) {
                float h3v = (nt < 4) ? h3a : h3b;
                #pragma unroll
                for (int j = 0; j < 2; ++j) {
                    float v = acc[mt][nt][hf*2 + j] + h3v;
                    s += v; q = fmaf(v, v, q);
                    if (MODE == 1) {
                        int nl = wn*64 + nt*8 + qcol*2 + j;
                        st[nl*128 + mloc] = __float2half(v);
                    } else {
                        if (nt < 4) mx0 = fmaxf(mx0, v); else mx1 = fmaxf(mx1, v);
                    }
                }
            }
            if (MODE == 2) {
                // reduce max across the 4 qcol lanes (same qrow)
                mx0 = fmaxf(mx0, __shfl_xor_sync(0xffffffffu, mx0, 1));
                mx0 = fmaxf(mx0, __shfl_xor_sync(0xffffffffu, mx0, 2));
                mx1 = fmaxf(mx1, __shfl_xor_sync(0xffffffffu, mx1, 1));
                mx1 = fmaxf(mx1, __shfl_xor_sync(0xffffffffu, mx1, 2));
                if (qcol == 0) {
                    int bsg = (n0c >> 5) + wn*2;
                    g_y4m[mg*(BB*NSAMP) + bsg]     = mx0;
                    g_y4m[mg*(BB*NSAMP) + bsg + 1] = mx1;
                }
            }
            redS[mloc*16 + wn*4 + qcol] = s;
            redQ[mloc*16 + wn*4 + qcol] = q;
        }
    }
    __syncthreads();
    if (MODE == 1) {
        // coalesced store of the 256x128 fp16 tile to g_y3h [n][512]
        #pragma unroll
        for (int i = 0; i < 16; ++i) {
            int u = tid + i*256;             // 0..4095
            int row = u >> 4, seg = u & 15;
            uint4 v = *(uint4*)(st + row*128 + seg*8);
            *(uint4*)(g_y3h + (size_t)(n0c + row)*512 + m0c + seg*8) = v;
        }
    }
    if (tid < 128) {
        float s = 0.f;
        #pragma unroll
        for (int i = 0; i < 16; ++i) s += redS[tid*16 + i];
        atomicAdd(&Su[m0c + tid], s);
    } else {
        int m = tid - 128;
        float q = 0.f;
        #pragma unroll
        for (int i = 0; i < 16; ++i) q += redQ[m*16 + i];
        atomicAdd(&Sq[m0c + m], q);
    }
}

// ---------------- fin2: out_feat = relu(aff4(y4max)) --------------------------
__global__ void k_fin2(float* __restrict__ out) {
    int c = blockIdx.x;        // 256
    int b = blockIdx.y;        // 4
    int s = threadIdx.x;       // 1024
    int bs = b*1024 + s;
    float v = g_y4m[c*(BB*NSAMP) + bs];
    float o = fmaxf(fmaf(v, g_s4[c], g_t4[c]), 0.f);
    out[(((b << 8) + c) << 10) + s] = o;
}

// ---------------- launcher ----------------------------------------------------
extern "C" void kernel_launch(void* const* d_in, const int* in_sizes, int n_in,
                              void* d_out, int out_size) {
    const float* p   = (const float*)d_in[0];
    const float* f   = (const float*)d_in[1];
    const float* w1  = (const float*)d_in[2];
    const float* w2  = (const float*)d_in[3];
    const float* b2  = (const float*)d_in[4];
    const float* g2  = (const float*)d_in[5];
    const float* be2 = (const float*)d_in[6];
    const float* w3  = (const float*)d_in[7];
    const float* g3  = (const float*)d_in[8];
    const float* be3 = (const float*)d_in[9];
    const float* w4  = (const float*)d_in[10];
    const float* g4  = (const float*)d_in[11];
    const float* be4 = (const float*)d_in[12];
    float* out = (float*)d_out;

    cudaFuncSetAttribute(k_mma<1>, cudaFuncAttributeMaxDynamicSharedMemorySize, MMA_SMEM);
    cudaFuncSetAttribute(k_mma<2>, cudaFuncAttributeMaxDynamicSharedMemorySize, MMA_SMEM);

    k_zero<<<1, 512>>>();
    k_w21<<<1, 256>>>(w1, w2);
    k_wsplit<<<512, 256>>>(w3, w4);
    k_fps<<<BB, 512>>>(p, out);                        // cntrd -> d_out[0..12288)
    k_knn<<<BB*NSAMP, 128>>>(p, out);
    k_gconv1<<<MTOT/64, 256>>>(p, f, b2);              // y1h raw fp16 + stats2
    k_params<2><<<2, 256>>>(g2, be2);
    k_c1<<<BB*NSAMP, 256>>>();                         // y1a fp16 + xm
    k_gemm0<<<dim3(4, 32), 256>>>(w3);                 // h3 = w3a @ xm
    k_mma<1><<<dim3(4, 512), 256, MMA_SMEM>>>();       // y3h raw fp16 + stats3
    k_params<3><<<2, 256>>>(g3, be3);
    k_c3<<<65536, 256>>>();                            // y3a fp16
    k_mma<2><<<dim3(2, 512), 256, MMA_SMEM>>>();       // y4max + stats4
    k_params<4><<<2, 256>>>(g4, be4);
    k_fin2<<<dim3(256, 4), 1024>>>(out + BB*NSAMP*3);
}